// round 9
// baseline (speedup 1.0000x reference)
#include <cuda_runtime.h>
#include <cuda_bf16.h>
#include <cstdint>

#define BB 4
#define SS 2048
#define DD 2048          // D_IN = D_STATE = D_OUT
#define NH 16
#define HH 128

// ------------------------- global scratch (no allocs) -----------------------
static __device__ float g_xp[(size_t)BB * SS * DD];                  // 64MB
static __device__ __nv_bfloat16 g_xh[(size_t)BB * SS * DD];          // 32MB
static __device__ __nv_bfloat16 g_xl[(size_t)BB * SS * DD];
static __device__ __nv_bfloat16 g_hsh[(size_t)BB * SS * DD];
static __device__ __nv_bfloat16 g_hsl[(size_t)BB * SS * DD];
static __device__ __nv_bfloat16 g_WiTh[(size_t)DD * DD];             // 8MB
static __device__ __nv_bfloat16 g_WiTl[(size_t)DD * DD];
static __device__ __nv_bfloat16 g_WoTh[(size_t)DD * DD];
static __device__ __nv_bfloat16 g_WoTl[(size_t)DD * DD];

typedef unsigned long long ull;

__device__ __forceinline__ ull pack2(float x, float y) {
    ull r; asm("mov.b64 %0, {%1,%2};" : "=l"(r) : "f"(x), "f"(y)); return r;
}
__device__ __forceinline__ float2 unpack2(ull v) {
    float lo, hi; asm("mov.b64 {%0,%1}, %2;" : "=f"(lo), "=f"(hi) : "l"(v));
    return make_float2(lo, hi);
}
__device__ __forceinline__ void fma2(ull& c, ull a, ull b) {
    asm("fma.rn.f32x2 %0, %1, %2, %3;" : "=l"(c) : "l"(a), "l"(b), "l"(c));
}

__device__ __forceinline__ uint32_t smem_u32(const void* p) {
    uint32_t a;
    asm("{ .reg .u64 t; cvta.to.shared.u64 t, %1; cvt.u32.u64 %0, t; }"
        : "=r"(a) : "l"(p));
    return a;
}
__device__ __forceinline__ void cp16(uint32_t s, const void* g) {
    asm volatile("cp.async.cg.shared.global [%0], [%1], 16;"
                 :: "r"(s), "l"(g) : "memory");
}
__device__ __forceinline__ void ldmx4(uint32_t* r, uint32_t addr) {
    asm volatile("ldmatrix.sync.aligned.m8n8.x4.shared.b16 {%0,%1,%2,%3}, [%4];"
                 : "=r"(r[0]), "=r"(r[1]), "=r"(r[2]), "=r"(r[3]) : "r"(addr));
}
__device__ __forceinline__ void mma_bf(float* c, const uint32_t* a,
                                       const uint32_t* b) {
    asm volatile(
        "mma.sync.aligned.m16n8k16.row.col.f32.bf16.bf16.f32 "
        "{%0,%1,%2,%3}, {%4,%5,%6,%7}, {%8,%9}, {%0,%1,%2,%3};"
        : "+f"(c[0]), "+f"(c[1]), "+f"(c[2]), "+f"(c[3])
        : "r"(a[0]), "r"(a[1]), "r"(a[2]), "r"(a[3]), "r"(b[0]), "r"(b[1]));
}

// ---------------------------------------------------------------------------
// elementwise split fp32 -> bf16 (hi, lo)
// ---------------------------------------------------------------------------
__global__ void __launch_bounds__(256)
split_f32(const float4* __restrict__ in, __nv_bfloat162* __restrict__ hi,
          __nv_bfloat162* __restrict__ lo) {
    int i = blockIdx.x * 256 + threadIdx.x;
    float4 v = in[i];
    __nv_bfloat16 h0 = __float2bfloat16(v.x), h1 = __float2bfloat16(v.y);
    __nv_bfloat16 h2 = __float2bfloat16(v.z), h3 = __float2bfloat16(v.w);
    hi[2 * i + 0] = __halves2bfloat162(h0, h1);
    hi[2 * i + 1] = __halves2bfloat162(h2, h3);
    lo[2 * i + 0] = __halves2bfloat162(
        __float2bfloat16(v.x - __bfloat162float(h0)),
        __float2bfloat16(v.y - __bfloat162float(h1)));
    lo[2 * i + 1] = __halves2bfloat162(
        __float2bfloat16(v.z - __bfloat162float(h2)),
        __float2bfloat16(v.w - __bfloat162float(h3)));
}

// ---------------------------------------------------------------------------
// transpose 2048x2048 fp32 + split -> bf16 hi/lo (out[n][k] = in[k][n])
// ---------------------------------------------------------------------------
__global__ void __launch_bounds__(256)
transpose_split(const float* __restrict__ in, __nv_bfloat16* __restrict__ oh,
                __nv_bfloat16* __restrict__ ol) {
    __shared__ float tile[32][33];
    int x = blockIdx.x * 32 + threadIdx.x;
    int y = blockIdx.y * 32 + threadIdx.y;
#pragma unroll
    for (int i = 0; i < 32; i += 8)
        tile[threadIdx.y + i][threadIdx.x] = in[(size_t)(y + i) * DD + x];
    __syncthreads();
    x = blockIdx.y * 32 + threadIdx.x;
    y = blockIdx.x * 32 + threadIdx.y;
#pragma unroll
    for (int i = 0; i < 32; i += 8) {
        float v = tile[threadIdx.x][threadIdx.y + i];
        __nv_bfloat16 h = __float2bfloat16(v);
        oh[(size_t)(y + i) * DD + x] = h;
        ol[(size_t)(y + i) * DD + x] =
            __float2bfloat16(v - __bfloat162float(h));
    }
}

// ---------------------------------------------------------------------------
// 3x bf16-split GEMM: C[M,2048] = A @ BT^T (+bias)
//   CTA tile 256x128, K_tile 32, 8 warps (4m x 2n, warp = 64x64),
//   2-stage cp.async double buffer (known-good control flow).
// ---------------------------------------------------------------------------
#define KT 32
#define PADK 40                         // smem row stride in bf16 (80B)
#define ROWB (PADK * 2)                 // 80
#define OP_AH 0
#define OP_AL 20480                     // 256*80
#define OP_BH 40960
#define OP_BL 51200                     // + 128*80
#define STAGEB 61440
#define NSTAGE 2
#define SMEMB (NSTAGE * STAGEB)         // 122880

template <bool BIAS>
__global__ void __launch_bounds__(256, 1)
gemm_bf3(const __nv_bfloat16* __restrict__ Ah,
         const __nv_bfloat16* __restrict__ Al,
         const __nv_bfloat16* __restrict__ Bh,
         const __nv_bfloat16* __restrict__ Bl,
         const float* __restrict__ bias, float* __restrict__ C) {
    extern __shared__ __align__(128) char smem[];
    const uint32_t sb = smem_u32(smem);
    const int tid = threadIdx.x;
    const int lane = tid & 31;
    const int wid = tid >> 5;
    const int wm = wid & 3;             // 4 m-blocks of 64 rows
    const int wn = wid >> 2;            // 2 n-blocks of 64 cols
    const size_t bm = (size_t)blockIdx.y * 256;
    const size_t bn = (size_t)blockIdx.x * 128;

    // copy mapping: A row = tid (4 chunks), B row = tid>>1 (2 chunks)
    const __nv_bfloat16* gAh = Ah + (bm + tid) * DD;
    const __nv_bfloat16* gAl = Al + (bm + tid) * DD;
    const int brow = tid >> 1;
    const int bc = (tid & 1) * 2;
    const __nv_bfloat16* gBh = Bh + (bn + brow) * DD + bc * 8;
    const __nv_bfloat16* gBl = Bl + (bn + brow) * DD + bc * 8;
    const uint32_t sA = sb + tid * ROWB;
    const uint32_t sB = sb + brow * ROWB + bc * 16;

    // fragment addresses
    const uint32_t aBase = sb + (wm * 64 + (lane & 15)) * ROWB +
                           (lane >> 4) * 16;
    const int n_off = (lane & 7) + ((lane >> 4) & 1) * 8;
    const int k_off = ((lane >> 3) & 1) * 16;
    const uint32_t bBase = sb + OP_BH + (wn * 64 + n_off) * ROWB + k_off;

    float acc[128];
#pragma unroll
    for (int i = 0; i < 128; i++) acc[i] = 0.0f;

    const int ntiles = DD / KT;  // 64

    // stage loader
    auto load_stage = [&](int stage, int t) {
        const uint32_t so = stage * STAGEB;
        const int ko = t * KT;
#pragma unroll
        for (int i = 0; i < 4; i++) {
            cp16(sA + OP_AH + so + i * 16, gAh + ko + i * 8);
            cp16(sA + OP_AL + so + i * 16, gAl + ko + i * 8);
        }
#pragma unroll
        for (int i = 0; i < 2; i++) {
            cp16(sB + OP_BH + so + i * 16, gBh + ko + i * 8);
            cp16(sB + OP_BL + so + i * 16, gBl + ko + i * 8);
        }
        asm volatile("cp.async.commit_group;" ::: "memory");
    };

    load_stage(0, 0);

    for (int t = 0; t < ntiles; t++) {
        asm volatile("cp.async.wait_group 0;" ::: "memory");
        __syncthreads();

        if (t + 1 < ntiles)
            load_stage((t + 1) & 1, t + 1);

        const uint32_t so = (t & 1) * STAGEB;
#pragma unroll
        for (int kk = 0; kk < 2; kk++) {
            uint32_t ah[4][4], al[4][4];
#pragma unroll
            for (int mt = 0; mt < 4; mt++) {
                ldmx4(ah[mt], aBase + so + mt * 16 * ROWB + kk * 32);
                ldmx4(al[mt], aBase + so + OP_AL + mt * 16 * ROWB + kk * 32);
            }
#pragma unroll
            for (int p = 0; p < 4; p++) {
                uint32_t bh[4], bl[4];
                ldmx4(bh, bBase + so + p * 16 * ROWB + kk * 32);
                ldmx4(bl, bBase + so + 10240 + p * 16 * ROWB + kk * 32);
#pragma unroll
                for (int mt = 0; mt < 4; mt++) {
                    float* c0 = &acc[(mt * 8 + 2 * p) * 4];
                    float* c1 = &acc[(mt * 8 + 2 * p + 1) * 4];
                    mma_bf(c0, ah[mt], bh + 0);
                    mma_bf(c1, ah[mt], bh + 2);
                    mma_bf(c0, al[mt], bh + 0);
                    mma_bf(c1, al[mt], bh + 2);
                    mma_bf(c0, ah[mt], bl + 0);
                    mma_bf(c1, ah[mt], bl + 2);
                }
            }
        }
        __syncthreads();
    }

    // epilogue
#pragma unroll
    for (int mt = 0; mt < 4; mt++) {
        const size_t r0 = bm + wm * 64 + mt * 16 + (lane >> 2);
#pragma unroll
        for (int nt = 0; nt < 8; nt++) {
            const size_t col = bn + wn * 64 + nt * 8 + (lane & 3) * 2;
            const float* a = &acc[(mt * 8 + nt) * 4];
            float2 v0 = make_float2(a[0], a[1]);
            float2 v1 = make_float2(a[2], a[3]);
            if (BIAS) {
                float2 bv = *(const float2*)&bias[col];
                v0.x += bv.x; v0.y += bv.y;
                v1.x += bv.x; v1.y += bv.y;
            }
            *(float2*)&C[r0 * DD + col] = v0;
            *(float2*)&C[(r0 + 8) * DD + col] = v1;
        }
    }
}

// ---------------------------------------------------------------------------
// Recurrence: 64 chains, W columns in regs; emits hs as bf16 hi/lo split.
// ---------------------------------------------------------------------------
__global__ void __launch_bounds__(128, 1)
rnn_kernel(const float* __restrict__ xp, const float* __restrict__ init_state,
           const float* __restrict__ state_w,
           __nv_bfloat16* __restrict__ hs_h, __nv_bfloat16* __restrict__ hs_l,
           float* __restrict__ out_state) {
    const int b = blockIdx.x >> 4;
    const int n = blockIdx.x & 15;
    const int j = threadIdx.x;

    __shared__ __align__(16) float h_sh[2][HH];

    ull w2[64];
    const float* W = state_w + (size_t)n * HH * HH + j;
#pragma unroll
    for (int m = 0; m < 64; m++)
        w2[m] = pack2(W[(2 * m) * HH], W[(2 * m + 1) * HH]);

    h_sh[0][j] = init_state[b * DD + n * HH + j];

    const float* xb = xp + ((size_t)b * SS * NH + n) * HH + j;
    __nv_bfloat16* hbh = hs_h + ((size_t)b * SS * NH + n) * HH + j;
    __nv_bfloat16* hbl = hs_l + ((size_t)b * SS * NH + n) * HH + j;

    float xq[8];
#pragma unroll
    for (int p = 0; p < 8; p++) xq[p] = xb[(size_t)p * DD];

    __syncthreads();

    int cur = 0;
    for (int t = 0; t < SS; t++) {
        const ulonglong2* hv = (const ulonglong2*)h_sh[cur];
        ull a0 = 0ull, a1 = 0ull, a2 = 0ull, a3 = 0ull;
#pragma unroll
        for (int m = 0; m < 32; m += 2) {
            ulonglong2 ha = hv[m];
            ulonglong2 hc = hv[m + 1];
            fma2(a0, ha.x, w2[2 * m]);
            fma2(a1, ha.y, w2[2 * m + 1]);
            fma2(a2, hc.x, w2[2 * m + 2]);
            fma2(a3, hc.y, w2[2 * m + 3]);
        }
        float2 f0 = unpack2(a0), f1 = unpack2(a1);
        float2 f2 = unpack2(a2), f3 = unpack2(a3);
        float sum = ((f0.x + f0.y) + (f1.x + f1.y)) +
                    ((f2.x + f2.y) + (f3.x + f3.y));

        float xv = xq[t & 7];
        if (t + 8 < SS) xq[t & 7] = xb[(size_t)(t + 8) * DD];

        float hn = tanhf(sum + xv);
        __nv_bfloat16 hh = __float2bfloat16(hn);
        hbh[(size_t)t * DD] = hh;
        hbl[(size_t)t * DD] = __float2bfloat16(hn - __bfloat162float(hh));

        const int nxt = cur ^ 1;
        h_sh[nxt][j] = hn;
        __syncthreads();
        cur = nxt;
    }

    if (out_state) out_state[b * DD + n * HH + j] = h_sh[cur][j];
}

// ---------------------------------------------------------------------------
extern "C" void kernel_launch(void* const* d_in, const int* in_sizes, int n_in,
                              void* d_out, int out_size) {
    const float* x = (const float*)d_in[0];
    const float* input_state = (const float*)d_in[1];
    const float* Wi = (const float*)d_in[2];
    const float* bias = (const float*)d_in[3];
    const float* state_w = (const float*)d_in[4];
    const float* Wo = (const float*)d_in[5];
    float* out = (float*)d_out;

    float* xp = nullptr;
    __nv_bfloat16 *xh, *xl, *hsh, *hsl, *WiTh, *WiTl, *WoTh, *WoTl;
    cudaGetSymbolAddress((void**)&xp, g_xp);
    cudaGetSymbolAddress((void**)&xh, g_xh);
    cudaGetSymbolAddress((void**)&xl, g_xl);
    cudaGetSymbolAddress((void**)&hsh, g_hsh);
    cudaGetSymbolAddress((void**)&hsl, g_hsl);
    cudaGetSymbolAddress((void**)&WiTh, g_WiTh);
    cudaGetSymbolAddress((void**)&WiTl, g_WiTl);
    cudaGetSymbolAddress((void**)&WoTh, g_WoTh);
    cudaGetSymbolAddress((void**)&WoTl, g_WoTl);

    cudaFuncSetAttribute(gemm_bf3<true>,
                         cudaFuncAttributeMaxDynamicSharedMemorySize, SMEMB);
    cudaFuncSetAttribute(gemm_bf3<false>,
                         cudaFuncAttributeMaxDynamicSharedMemorySize, SMEMB);

    const size_t out_elems = (size_t)BB * SS * DD;
    float* state_out = nullptr;
    if ((size_t)out_size >= out_elems + (size_t)BB * DD)
        state_out = out + out_elems;

    // 0) operand preparation
    split_f32<<<(BB * SS * DD) / 4 / 256, 256>>>(
        (const float4*)x, (__nv_bfloat162*)xh, (__nv_bfloat162*)xl);
    dim3 tgrid(DD / 32, DD / 32), tblk(32, 8);
    transpose_split<<<tgrid, tblk>>>(Wi, WiTh, WiTl);
    transpose_split<<<tgrid, tblk>>>(Wo, WoTh, WoTl);

    dim3 ggrid(DD / 128, (BB * SS) / 256);  // (16, 32) = 512 CTAs
    // 1) xp = x @ Wi + b
    gemm_bf3<true><<<ggrid, 256, SMEMB>>>(xh, xl, WiTh, WiTl, bias, xp);
    // 2) recurrence -> hs (bf16 hi/lo) + final state
    rnn_kernel<<<64, 128>>>(xp, input_state, state_w, hsh, hsl, state_out);
    // 3) out = hs @ Wo
    gemm_bf3<false><<<ggrid, 256, SMEMB>>>(hsh, hsl, WoTh, WoTl, nullptr, out);
}

// round 10
// speedup vs baseline: 1.0068x; 1.0068x over previous
#include <cuda_runtime.h>
#include <cuda_bf16.h>
#include <cstdint>

#define BB 4
#define SS 2048
#define DD 2048          // D_IN = D_STATE = D_OUT
#define NH 16
#define HH 128

// ------------------------- global scratch (no allocs) -----------------------
static __device__ float g_xp[(size_t)BB * SS * DD];                  // 64MB
static __device__ __nv_bfloat16 g_xh[(size_t)BB * SS * DD];          // 32MB
static __device__ __nv_bfloat16 g_xl[(size_t)BB * SS * DD];
static __device__ __nv_bfloat16 g_hsh[(size_t)BB * SS * DD];
static __device__ __nv_bfloat16 g_hsl[(size_t)BB * SS * DD];
static __device__ __nv_bfloat16 g_WiTh[(size_t)DD * DD];             // 8MB
static __device__ __nv_bfloat16 g_WiTl[(size_t)DD * DD];
static __device__ __nv_bfloat16 g_WoTh[(size_t)DD * DD];
static __device__ __nv_bfloat16 g_WoTl[(size_t)DD * DD];

typedef unsigned long long ull;

__device__ __forceinline__ ull pack2(float x, float y) {
    ull r; asm("mov.b64 %0, {%1,%2};" : "=l"(r) : "f"(x), "f"(y)); return r;
}
__device__ __forceinline__ float2 unpack2(ull v) {
    float lo, hi; asm("mov.b64 {%0,%1}, %2;" : "=f"(lo), "=f"(hi) : "l"(v));
    return make_float2(lo, hi);
}
__device__ __forceinline__ void fma2(ull& c, ull a, ull b) {
    asm("fma.rn.f32x2 %0, %1, %2, %3;" : "=l"(c) : "l"(a), "l"(b), "l"(c));
}

__device__ __forceinline__ uint32_t smem_u32(const void* p) {
    uint32_t a;
    asm("{ .reg .u64 t; cvta.to.shared.u64 t, %1; cvt.u32.u64 %0, t; }"
        : "=r"(a) : "l"(p));
    return a;
}
__device__ __forceinline__ void cp16(uint32_t s, const void* g) {
    asm volatile("cp.async.cg.shared.global [%0], [%1], 16;"
                 :: "r"(s), "l"(g) : "memory");
}
__device__ __forceinline__ void ldmx4(uint32_t* r, uint32_t addr) {
    asm volatile("ldmatrix.sync.aligned.m8n8.x4.shared.b16 {%0,%1,%2,%3}, [%4];"
                 : "=r"(r[0]), "=r"(r[1]), "=r"(r[2]), "=r"(r[3]) : "r"(addr));
}
__device__ __forceinline__ void mma_bf(float* c, const uint32_t* a,
                                       const uint32_t* b) {
    asm volatile(
        "mma.sync.aligned.m16n8k16.row.col.f32.bf16.bf16.f32 "
        "{%0,%1,%2,%3}, {%4,%5,%6,%7}, {%8,%9}, {%0,%1,%2,%3};"
        : "+f"(c[0]), "+f"(c[1]), "+f"(c[2]), "+f"(c[3])
        : "r"(a[0]), "r"(a[1]), "r"(a[2]), "r"(a[3]), "r"(b[0]), "r"(b[1]));
}

// ---------------------------------------------------------------------------
// elementwise split fp32 -> bf16 (hi, lo)
// ---------------------------------------------------------------------------
__global__ void __launch_bounds__(256)
split_f32(const float4* __restrict__ in, __nv_bfloat162* __restrict__ hi,
          __nv_bfloat162* __restrict__ lo) {
    int i = blockIdx.x * 256 + threadIdx.x;
    float4 v = in[i];
    __nv_bfloat16 h0 = __float2bfloat16(v.x), h1 = __float2bfloat16(v.y);
    __nv_bfloat16 h2 = __float2bfloat16(v.z), h3 = __float2bfloat16(v.w);
    hi[2 * i + 0] = __halves2bfloat162(h0, h1);
    hi[2 * i + 1] = __halves2bfloat162(h2, h3);
    lo[2 * i + 0] = __halves2bfloat162(
        __float2bfloat16(v.x - __bfloat162float(h0)),
        __float2bfloat16(v.y - __bfloat162float(h1)));
    lo[2 * i + 1] = __halves2bfloat162(
        __float2bfloat16(v.z - __bfloat162float(h2)),
        __float2bfloat16(v.w - __bfloat162float(h3)));
}

// ---------------------------------------------------------------------------
// transpose 2048x2048 fp32 + split -> bf16 hi/lo (out[n][k] = in[k][n])
// ---------------------------------------------------------------------------
__global__ void __launch_bounds__(256)
transpose_split(const float* __restrict__ in, __nv_bfloat16* __restrict__ oh,
                __nv_bfloat16* __restrict__ ol) {
    __shared__ float tile[32][33];
    int x = blockIdx.x * 32 + threadIdx.x;
    int y = blockIdx.y * 32 + threadIdx.y;
#pragma unroll
    for (int i = 0; i < 32; i += 8)
        tile[threadIdx.y + i][threadIdx.x] = in[(size_t)(y + i) * DD + x];
    __syncthreads();
    x = blockIdx.y * 32 + threadIdx.x;
    y = blockIdx.x * 32 + threadIdx.y;
#pragma unroll
    for (int i = 0; i < 32; i += 8) {
        float v = tile[threadIdx.x][threadIdx.y + i];
        __nv_bfloat16 h = __float2bfloat16(v);
        oh[(size_t)(y + i) * DD + x] = h;
        ol[(size_t)(y + i) * DD + x] =
            __float2bfloat16(v - __bfloat162float(h));
    }
}

// ---------------------------------------------------------------------------
// 3x bf16-split GEMM: C[M,2048] = A @ BT^T (+bias)
//   CTA tile 256x128, K_tile 32, 8 warps (4m x 2n, warp = 64x64),
//   2-stage cp.async double buffer (known-good control flow).
// ---------------------------------------------------------------------------
#define KT 32
#define PADK 40                         // smem row stride in bf16 (80B)
#define ROWB (PADK * 2)                 // 80
#define OP_AH 0
#define OP_AL 20480                     // 256*80
#define OP_BH 40960
#define OP_BL 51200                     // + 128*80
#define STAGEB 61440
#define NSTAGE 2
#define SMEMB (NSTAGE * STAGEB)         // 122880

template <bool BIAS>
__global__ void __launch_bounds__(256, 1)
gemm_bf3(const __nv_bfloat16* __restrict__ Ah,
         const __nv_bfloat16* __restrict__ Al,
         const __nv_bfloat16* __restrict__ Bh,
         const __nv_bfloat16* __restrict__ Bl,
         const float* __restrict__ bias, float* __restrict__ C) {
    extern __shared__ __align__(128) char smem[];
    const uint32_t sb = smem_u32(smem);
    const int tid = threadIdx.x;
    const int lane = tid & 31;
    const int wid = tid >> 5;
    const int wm = wid & 3;             // 4 m-blocks of 64 rows
    const int wn = wid >> 2;            // 2 n-blocks of 64 cols
    const size_t bm = (size_t)blockIdx.y * 256;
    const size_t bn = (size_t)blockIdx.x * 128;

    // copy mapping: A row = tid (4 chunks), B row = tid>>1 (2 chunks)
    const __nv_bfloat16* gAh = Ah + (bm + tid) * DD;
    const __nv_bfloat16* gAl = Al + (bm + tid) * DD;
    const int brow = tid >> 1;
    const int bc = (tid & 1) * 2;
    const __nv_bfloat16* gBh = Bh + (bn + brow) * DD + bc * 8;
    const __nv_bfloat16* gBl = Bl + (bn + brow) * DD + bc * 8;
    const uint32_t sA = sb + tid * ROWB;
    const uint32_t sB = sb + brow * ROWB + bc * 16;

    // fragment addresses
    const uint32_t aBase = sb + (wm * 64 + (lane & 15)) * ROWB +
                           (lane >> 4) * 16;
    const int n_off = (lane & 7) + ((lane >> 4) & 1) * 8;
    const int k_off = ((lane >> 3) & 1) * 16;
    const uint32_t bBase = sb + OP_BH + (wn * 64 + n_off) * ROWB + k_off;

    float acc[128];
#pragma unroll
    for (int i = 0; i < 128; i++) acc[i] = 0.0f;

    const int ntiles = DD / KT;  // 64

    // stage loader
    auto load_stage = [&](int stage, int t) {
        const uint32_t so = stage * STAGEB;
        const int ko = t * KT;
#pragma unroll
        for (int i = 0; i < 4; i++) {
            cp16(sA + OP_AH + so + i * 16, gAh + ko + i * 8);
            cp16(sA + OP_AL + so + i * 16, gAl + ko + i * 8);
        }
#pragma unroll
        for (int i = 0; i < 2; i++) {
            cp16(sB + OP_BH + so + i * 16, gBh + ko + i * 8);
            cp16(sB + OP_BL + so + i * 16, gBl + ko + i * 8);
        }
        asm volatile("cp.async.commit_group;" ::: "memory");
    };

    load_stage(0, 0);

    for (int t = 0; t < ntiles; t++) {
        asm volatile("cp.async.wait_group 0;" ::: "memory");
        __syncthreads();

        if (t + 1 < ntiles)
            load_stage((t + 1) & 1, t + 1);

        const uint32_t so = (t & 1) * STAGEB;
#pragma unroll
        for (int kk = 0; kk < 2; kk++) {
            uint32_t ah[4][4], al[4][4];
#pragma unroll
            for (int mt = 0; mt < 4; mt++) {
                ldmx4(ah[mt], aBase + so + mt * 16 * ROWB + kk * 32);
                ldmx4(al[mt], aBase + so + OP_AL + mt * 16 * ROWB + kk * 32);
            }
#pragma unroll
            for (int p = 0; p < 4; p++) {
                uint32_t bh[4], bl[4];
                ldmx4(bh, bBase + so + p * 16 * ROWB + kk * 32);
                ldmx4(bl, bBase + so + 10240 + p * 16 * ROWB + kk * 32);
#pragma unroll
                for (int mt = 0; mt < 4; mt++) {
                    float* c0 = &acc[(mt * 8 + 2 * p) * 4];
                    float* c1 = &acc[(mt * 8 + 2 * p + 1) * 4];
                    mma_bf(c0, ah[mt], bh + 0);
                    mma_bf(c1, ah[mt], bh + 2);
                    mma_bf(c0, al[mt], bh + 0);
                    mma_bf(c1, al[mt], bh + 2);
                    mma_bf(c0, ah[mt], bl + 0);
                    mma_bf(c1, ah[mt], bl + 2);
                }
            }
        }
        __syncthreads();
    }

    // epilogue
#pragma unroll
    for (int mt = 0; mt < 4; mt++) {
        const size_t r0 = bm + wm * 64 + mt * 16 + (lane >> 2);
#pragma unroll
        for (int nt = 0; nt < 8; nt++) {
            const size_t col = bn + wn * 64 + nt * 8 + (lane & 3) * 2;
            const float* a = &acc[(mt * 8 + nt) * 4];
            float2 v0 = make_float2(a[0], a[1]);
            float2 v1 = make_float2(a[2], a[3]);
            if (BIAS) {
                float2 bv = *(const float2*)&bias[col];
                v0.x += bv.x; v0.y += bv.y;
                v1.x += bv.x; v1.y += bv.y;
            }
            *(float2*)&C[r0 * DD + col] = v0;
            *(float2*)&C[(r0 + 8) * DD + col] = v1;
        }
    }
}

// ---------------------------------------------------------------------------
// Recurrence: 64 chains, W columns in regs; emits hs as bf16 hi/lo split.
// ---------------------------------------------------------------------------
__global__ void __launch_bounds__(128, 1)
rnn_kernel(const float* __restrict__ xp, const float* __restrict__ init_state,
           const float* __restrict__ state_w,
           __nv_bfloat16* __restrict__ hs_h, __nv_bfloat16* __restrict__ hs_l,
           float* __restrict__ out_state) {
    const int b = blockIdx.x >> 4;
    const int n = blockIdx.x & 15;
    const int j = threadIdx.x;

    __shared__ __align__(16) float h_sh[2][HH];

    ull w2[64];
    const float* W = state_w + (size_t)n * HH * HH + j;
#pragma unroll
    for (int m = 0; m < 64; m++)
        w2[m] = pack2(W[(2 * m) * HH], W[(2 * m + 1) * HH]);

    h_sh[0][j] = init_state[b * DD + n * HH + j];

    const float* xb = xp + ((size_t)b * SS * NH + n) * HH + j;
    __nv_bfloat16* hbh = hs_h + ((size_t)b * SS * NH + n) * HH + j;
    __nv_bfloat16* hbl = hs_l + ((size_t)b * SS * NH + n) * HH + j;

    float xq[8];
#pragma unroll
    for (int p = 0; p < 8; p++) xq[p] = xb[(size_t)p * DD];

    __syncthreads();

    int cur = 0;
    for (int t = 0; t < SS; t++) {
        const ulonglong2* hv = (const ulonglong2*)h_sh[cur];
        ull a0 = 0ull, a1 = 0ull, a2 = 0ull, a3 = 0ull;
#pragma unroll
        for (int m = 0; m < 32; m += 2) {
            ulonglong2 ha = hv[m];
            ulonglong2 hc = hv[m + 1];
            fma2(a0, ha.x, w2[2 * m]);
            fma2(a1, ha.y, w2[2 * m + 1]);
            fma2(a2, hc.x, w2[2 * m + 2]);
            fma2(a3, hc.y, w2[2 * m + 3]);
        }
        float2 f0 = unpack2(a0), f1 = unpack2(a1);
        float2 f2 = unpack2(a2), f3 = unpack2(a3);
        float sum = ((f0.x + f0.y) + (f1.x + f1.y)) +
                    ((f2.x + f2.y) + (f3.x + f3.y));

        float xv = xq[t & 7];
        if (t + 8 < SS) xq[t & 7] = xb[(size_t)(t + 8) * DD];

        float hn = tanhf(sum + xv);
        __nv_bfloat16 hh = __float2bfloat16(hn);
        hbh[(size_t)t * DD] = hh;
        hbl[(size_t)t * DD] = __float2bfloat16(hn - __bfloat162float(hh));

        const int nxt = cur ^ 1;
        h_sh[nxt][j] = hn;
        __syncthreads();
        cur = nxt;
    }

    if (out_state) out_state[b * DD + n * HH + j] = h_sh[cur][j];
}

// ---------------------------------------------------------------------------
extern "C" void kernel_launch(void* const* d_in, const int* in_sizes, int n_in,
                              void* d_out, int out_size) {
    const float* x = (const float*)d_in[0];
    const float* input_state = (const float*)d_in[1];
    const float* Wi = (const float*)d_in[2];
    const float* bias = (const float*)d_in[3];
    const float* state_w = (const float*)d_in[4];
    const float* Wo = (const float*)d_in[5];
    float* out = (float*)d_out;

    float* xp = nullptr;
    __nv_bfloat16 *xh, *xl, *hsh, *hsl, *WiTh, *WiTl, *WoTh, *WoTl;
    cudaGetSymbolAddress((void**)&xp, g_xp);
    cudaGetSymbolAddress((void**)&xh, g_xh);
    cudaGetSymbolAddress((void**)&xl, g_xl);
    cudaGetSymbolAddress((void**)&hsh, g_hsh);
    cudaGetSymbolAddress((void**)&hsl, g_hsl);
    cudaGetSymbolAddress((void**)&WiTh, g_WiTh);
    cudaGetSymbolAddress((void**)&WiTl, g_WiTl);
    cudaGetSymbolAddress((void**)&WoTh, g_WoTh);
    cudaGetSymbolAddress((void**)&WoTl, g_WoTl);

    cudaFuncSetAttribute(gemm_bf3<true>,
                         cudaFuncAttributeMaxDynamicSharedMemorySize, SMEMB);
    cudaFuncSetAttribute(gemm_bf3<false>,
                         cudaFuncAttributeMaxDynamicSharedMemorySize, SMEMB);

    const size_t out_elems = (size_t)BB * SS * DD;
    float* state_out = nullptr;
    if ((size_t)out_size >= out_elems + (size_t)BB * DD)
        state_out = out + out_elems;

    // 0) operand preparation
    split_f32<<<(BB * SS * DD) / 4 / 256, 256>>>(
        (const float4*)x, (__nv_bfloat162*)xh, (__nv_bfloat162*)xl);
    dim3 tgrid(DD / 32, DD / 32), tblk(32, 8);
    transpose_split<<<tgrid, tblk>>>(Wi, WiTh, WiTl);
    transpose_split<<<tgrid, tblk>>>(Wo, WoTh, WoTl);

    dim3 ggrid(DD / 128, (BB * SS) / 256);  // (16, 32) = 512 CTAs
    // 1) xp = x @ Wi + b
    gemm_bf3<true><<<ggrid, 256, SMEMB>>>(xh, xl, WiTh, WiTl, bias, xp);
    // 2) recurrence -> hs (bf16 hi/lo) + final state
    rnn_kernel<<<64, 128>>>(xp, input_state, state_w, hsh, hsl, state_out);
    // 3) out = hs @ Wo
    gemm_bf3<false><<<ggrid, 256, SMEMB>>>(hsh, hsl, WoTh, WoTl, nullptr, out);
}

// round 12
// speedup vs baseline: 1.2164x; 1.2081x over previous
#include <cuda_runtime.h>
#include <cuda_bf16.h>
#include <cstdint>

#define BB 4
#define SS 2048
#define DD 2048          // D_IN = D_STATE = D_OUT
#define NH 16
#define HH 128

// ------------------------- global scratch (no allocs) -----------------------
static __device__ float g_xp[(size_t)BB * SS * DD];                  // 64MB
static __device__ __nv_bfloat16 g_xh[(size_t)BB * SS * DD];          // 32MB
static __device__ __nv_bfloat16 g_xl[(size_t)BB * SS * DD];
static __device__ __nv_bfloat16 g_hsh[(size_t)BB * SS * DD];
static __device__ __nv_bfloat16 g_hsl[(size_t)BB * SS * DD];
static __device__ __nv_bfloat16 g_WiTh[(size_t)DD * DD];             // 8MB
static __device__ __nv_bfloat16 g_WiTl[(size_t)DD * DD];
static __device__ __nv_bfloat16 g_WoTh[(size_t)DD * DD];
static __device__ __nv_bfloat16 g_WoTl[(size_t)DD * DD];

typedef unsigned long long ull;

__device__ __forceinline__ ull pack2(float x, float y) {
    ull r; asm("mov.b64 %0, {%1,%2};" : "=l"(r) : "f"(x), "f"(y)); return r;
}
__device__ __forceinline__ float2 unpack2(ull v) {
    float lo, hi; asm("mov.b64 {%0,%1}, %2;" : "=f"(lo), "=f"(hi) : "l"(v));
    return make_float2(lo, hi);
}
__device__ __forceinline__ void fma2(ull& c, ull a, ull b) {
    asm("fma.rn.f32x2 %0, %1, %2, %3;" : "=l"(c) : "l"(a), "l"(b), "l"(c));
}

__device__ __forceinline__ uint32_t smem_u32(const void* p) {
    uint32_t a;
    asm("{ .reg .u64 t; cvta.to.shared.u64 t, %1; cvt.u32.u64 %0, t; }"
        : "=r"(a) : "l"(p));
    return a;
}
__device__ __forceinline__ void cp16(uint32_t s, const void* g) {
    asm volatile("cp.async.cg.shared.global [%0], [%1], 16;"
                 :: "r"(s), "l"(g) : "memory");
}
__device__ __forceinline__ void ldmx4(uint32_t* r, uint32_t addr) {
    asm volatile("ldmatrix.sync.aligned.m8n8.x4.shared.b16 {%0,%1,%2,%3}, [%4];"
                 : "=r"(r[0]), "=r"(r[1]), "=r"(r[2]), "=r"(r[3]) : "r"(addr));
}
__device__ __forceinline__ void mma_bf(float* c, const uint32_t* a,
                                       const uint32_t* b) {
    asm volatile(
        "mma.sync.aligned.m16n8k16.row.col.f32.bf16.bf16.f32 "
        "{%0,%1,%2,%3}, {%4,%5,%6,%7}, {%8,%9}, {%0,%1,%2,%3};"
        : "+f"(c[0]), "+f"(c[1]), "+f"(c[2]), "+f"(c[3])
        : "r"(a[0]), "r"(a[1]), "r"(a[2]), "r"(a[3]), "r"(b[0]), "r"(b[1]));
}

// ---------------------------------------------------------------------------
// elementwise split fp32 -> bf16 (hi, lo)
// ---------------------------------------------------------------------------
__global__ void __launch_bounds__(256)
split_f32(const float4* __restrict__ in, __nv_bfloat162* __restrict__ hi,
          __nv_bfloat162* __restrict__ lo) {
    int i = blockIdx.x * 256 + threadIdx.x;
    float4 v = in[i];
    __nv_bfloat16 h0 = __float2bfloat16(v.x), h1 = __float2bfloat16(v.y);
    __nv_bfloat16 h2 = __float2bfloat16(v.z), h3 = __float2bfloat16(v.w);
    hi[2 * i + 0] = __halves2bfloat162(h0, h1);
    hi[2 * i + 1] = __halves2bfloat162(h2, h3);
    lo[2 * i + 0] = __halves2bfloat162(
        __float2bfloat16(v.x - __bfloat162float(h0)),
        __float2bfloat16(v.y - __bfloat162float(h1)));
    lo[2 * i + 1] = __halves2bfloat162(
        __float2bfloat16(v.z - __bfloat162float(h2)),
        __float2bfloat16(v.w - __bfloat162float(h3)));
}

// ---------------------------------------------------------------------------
// transpose 2048x2048 fp32 + split -> bf16 hi/lo (out[n][k] = in[k][n])
// ---------------------------------------------------------------------------
__global__ void __launch_bounds__(256)
transpose_split(const float* __restrict__ in, __nv_bfloat16* __restrict__ oh,
                __nv_bfloat16* __restrict__ ol) {
    __shared__ float tile[32][33];
    int x = blockIdx.x * 32 + threadIdx.x;
    int y = blockIdx.y * 32 + threadIdx.y;
#pragma unroll
    for (int i = 0; i < 32; i += 8)
        tile[threadIdx.y + i][threadIdx.x] = in[(size_t)(y + i) * DD + x];
    __syncthreads();
    x = blockIdx.y * 32 + threadIdx.x;
    y = blockIdx.x * 32 + threadIdx.y;
#pragma unroll
    for (int i = 0; i < 32; i += 8) {
        float v = tile[threadIdx.x][threadIdx.y + i];
        __nv_bfloat16 h = __float2bfloat16(v);
        oh[(size_t)(y + i) * DD + x] = h;
        ol[(size_t)(y + i) * DD + x] =
            __float2bfloat16(v - __bfloat162float(h));
    }
}

// ---------------------------------------------------------------------------
// 3x bf16-split GEMM (exact round-5 config, proven 611us/GEMM):
//   128x128 CTA tile, K_tile 32, 8 warps (4m x 2n, warp = 32x64),
//   2-stage cp.async, 2 CTAs/SM.
// ---------------------------------------------------------------------------
#define KT 32
#define PADK 40                         // smem row stride in bf16 elems (80B)
#define OPB (128 * PADK * 2)            // 10240 B per operand tile
#define STAGEB (4 * OPB)                // 40960 B
#define SMEMB (2 * STAGEB)              // 81920 B

template <bool BIAS>
__global__ void __launch_bounds__(256, 2)
gemm_bf3(const __nv_bfloat16* __restrict__ Ah,
         const __nv_bfloat16* __restrict__ Al,
         const __nv_bfloat16* __restrict__ Bh,
         const __nv_bfloat16* __restrict__ Bl,
         const float* __restrict__ bias, float* __restrict__ C) {
    extern __shared__ __align__(128) char smem[];
    const uint32_t sb = smem_u32(smem);
    const int tid = threadIdx.x;
    const int lane = tid & 31;
    const int wid = tid >> 5;
    const int wm = wid & 3;             // 4 m-blocks of 32 rows
    const int wn = wid >> 2;            // 2 n-blocks of 64 cols
    const size_t bm = (size_t)blockIdx.y * 128;
    const size_t bn = (size_t)blockIdx.x * 128;

    // per-thread cp.async mapping: 2 16B chunks per operand
    const __nv_bfloat16* gsrc[4][2];
    uint32_t sdst[4][2];
    {
        const __nv_bfloat16* bases[4] = {Ah, Al, Bh, Bl};
#pragma unroll
        for (int op = 0; op < 4; op++)
#pragma unroll
            for (int i = 0; i < 2; i++) {
                int idx = tid * 2 + i;
                int r = idx >> 2, c = idx & 3;
                size_t grow = (op < 2 ? bm : bn) + r;
                gsrc[op][i] = bases[op] + grow * DD + c * 8;
                sdst[op][i] = sb + op * OPB + r * (PADK * 2) + c * 16;
            }
    }

    // fragment smem addresses
    const uint32_t aAddr = sb + (wm * 32 + (lane & 15)) * (PADK * 2) +
                           (lane >> 4) * 16;
    const int n_off = (lane & 7) + ((lane >> 4) & 1) * 8;
    const int k_off = ((lane >> 3) & 1) * 16;
    const uint32_t bAddr = sb + 2 * OPB + (wn * 64 + n_off) * (PADK * 2) + k_off;

    float acc[64];
#pragma unroll
    for (int i = 0; i < 64; i++) acc[i] = 0.0f;

    // prologue: stage 0 <- k-tile 0
#pragma unroll
    for (int op = 0; op < 4; op++)
#pragma unroll
        for (int i = 0; i < 2; i++)
            cp16(sdst[op][i], gsrc[op][i]);
    asm volatile("cp.async.commit_group;" ::: "memory");

    const int ntiles = DD / KT;  // 64
    for (int t = 0; t < ntiles; t++) {
        asm volatile("cp.async.wait_group 0;" ::: "memory");
        __syncthreads();

        if (t + 1 < ntiles) {
            const uint32_t so = ((t + 1) & 1) * STAGEB;
            const int ko = (t + 1) * KT;
#pragma unroll
            for (int op = 0; op < 4; op++)
#pragma unroll
                for (int i = 0; i < 2; i++)
                    cp16(sdst[op][i] + so, gsrc[op][i] + ko);
            asm volatile("cp.async.commit_group;" ::: "memory");
        }

        const uint32_t so = (t & 1) * STAGEB;
#pragma unroll
        for (int kk = 0; kk < 2; kk++) {
            uint32_t ah[2][4], al[2][4];
            ldmx4(ah[0], aAddr + so + kk * 32);
            ldmx4(ah[1], aAddr + so + 16 * (PADK * 2) + kk * 32);
            ldmx4(al[0], aAddr + so + OPB + kk * 32);
            ldmx4(al[1], aAddr + so + OPB + 16 * (PADK * 2) + kk * 32);
#pragma unroll
            for (int p = 0; p < 4; p++) {
                uint32_t bh[4], bl[4];
                ldmx4(bh, bAddr + so + p * 16 * (PADK * 2) + kk * 32);
                ldmx4(bl, bAddr + so + OPB + p * 16 * (PADK * 2) + kk * 32);
#pragma unroll
                for (int mt = 0; mt < 2; mt++) {
                    float* c0 = &acc[(mt * 8 + 2 * p) * 4];
                    float* c1 = &acc[(mt * 8 + 2 * p + 1) * 4];
                    mma_bf(c0, ah[mt], bh + 0);
                    mma_bf(c1, ah[mt], bh + 2);
                    mma_bf(c0, al[mt], bh + 0);
                    mma_bf(c1, al[mt], bh + 2);
                    mma_bf(c0, ah[mt], bl + 0);
                    mma_bf(c1, ah[mt], bl + 2);
                }
            }
        }
        __syncthreads();
    }

    // epilogue
#pragma unroll
    for (int mt = 0; mt < 2; mt++) {
        const size_t r0 = bm + wm * 32 + mt * 16 + (lane >> 2);
#pragma unroll
        for (int nt = 0; nt < 8; nt++) {
            const size_t col = bn + wn * 64 + nt * 8 + (lane & 3) * 2;
            const float* a = &acc[(mt * 8 + nt) * 4];
            float2 v0 = make_float2(a[0], a[1]);
            float2 v1 = make_float2(a[2], a[3]);
            if (BIAS) {
                float2 bv = *(const float2*)&bias[col];
                v0.x += bv.x; v0.y += bv.y;
                v1.x += bv.x; v1.y += bv.y;
            }
            *(float2*)&C[r0 * DD + col] = v0;
            *(float2*)&C[(r0 + 8) * DD + col] = v1;
        }
    }
}

// ---------------------------------------------------------------------------
// Recurrence v2: 64 CTAs x 256 threads. Thread pair (2k, 2k+1) owns output
// column k; each half accumulates 64 of 128 rows (32 fma2, 4 chains x 8),
// combined with one shfl.xor. Halves per-thread issue count and dep depth
// vs the 128-thread version. h reads remain smem broadcasts.
// ---------------------------------------------------------------------------
__global__ void __launch_bounds__(256, 1)
rnn_kernel(const float* __restrict__ xp, const float* __restrict__ init_state,
           const float* __restrict__ state_w,
           __nv_bfloat16* __restrict__ hs_h, __nv_bfloat16* __restrict__ hs_l,
           float* __restrict__ out_state) {
    const int b = blockIdx.x >> 4;
    const int n = blockIdx.x & 15;
    const int tid = threadIdx.x;
    const int j = tid >> 1;             // output column 0..127
    const int half = tid & 1;           // row half: 0 -> rows 0..63, 1 -> 64..127

    __shared__ __align__(16) float h_sh[2][HH];

    // W[n] column j, rows half*64 .. half*64+63, as 32 packed pairs
    ull w2[32];
    const float* W = state_w + (size_t)n * HH * HH + half * 64 * HH + j;
#pragma unroll
    for (int m = 0; m < 32; m++)
        w2[m] = pack2(W[(2 * m) * HH], W[(2 * m + 1) * HH]);

    if (half == 0) h_sh[0][j] = init_state[b * DD + n * HH + j];

    const float* xb = xp + ((size_t)b * SS * NH + n) * HH + j;  // stride DD
    __nv_bfloat16* hbh = hs_h + ((size_t)b * SS * NH + n) * HH + j;
    __nv_bfloat16* hbl = hs_l + ((size_t)b * SS * NH + n) * HH + j;

    float xq[8];
#pragma unroll
    for (int p = 0; p < 8; p++) xq[p] = xb[(size_t)p * DD];

    __syncthreads();

    int cur = 0;
    for (int t = 0; t < SS; t++) {
        // this half's 64 h values = 16 LDS.128 (broadcast across pairs)
        const ulonglong2* hv = (const ulonglong2*)&h_sh[cur][half * 64];
        ull a0 = 0ull, a1 = 0ull, a2 = 0ull, a3 = 0ull;
#pragma unroll
        for (int q = 0; q < 16; q += 4) {
            ulonglong2 h0 = hv[q + 0];
            ulonglong2 h1 = hv[q + 1];
            ulonglong2 h2 = hv[q + 2];
            ulonglong2 h3 = hv[q + 3];
            fma2(a0, h0.x, w2[2 * q + 0]);
            fma2(a1, h0.y, w2[2 * q + 1]);
            fma2(a2, h1.x, w2[2 * q + 2]);
            fma2(a3, h1.y, w2[2 * q + 3]);
            fma2(a0, h2.x, w2[2 * q + 4]);
            fma2(a1, h2.y, w2[2 * q + 5]);
            fma2(a2, h3.x, w2[2 * q + 6]);
            fma2(a3, h3.y, w2[2 * q + 7]);
        }
        float2 f0 = unpack2(a0), f1 = unpack2(a1);
        float2 f2 = unpack2(a2), f3 = unpack2(a3);
        float s = ((f0.x + f0.y) + (f1.x + f1.y)) +
                  ((f2.x + f2.y) + (f3.x + f3.y));
        // combine the two halves (lanes 2k <-> 2k+1)
        s += __shfl_xor_sync(0xFFFFFFFFu, s, 1);

        float xv = xq[t & 7];
        if (t + 8 < SS) xq[t & 7] = xb[(size_t)(t + 8) * DD];

        float hn = tanhf(s + xv);
        __nv_bfloat16 hh = __float2bfloat16(hn);
        if (half == 0) {
            hbh[(size_t)t * DD] = hh;
            h_sh[cur ^ 1][j] = hn;
        } else {
            hbl[(size_t)t * DD] =
                __float2bfloat16(hn - __bfloat162float(hh));
        }
        __syncthreads();
        cur ^= 1;
    }

    if (out_state && half == 0)
        out_state[b * DD + n * HH + j] = h_sh[cur][j];
}

// ---------------------------------------------------------------------------
extern "C" void kernel_launch(void* const* d_in, const int* in_sizes, int n_in,
                              void* d_out, int out_size) {
    const float* x = (const float*)d_in[0];
    const float* input_state = (const float*)d_in[1];
    const float* Wi = (const float*)d_in[2];
    const float* bias = (const float*)d_in[3];
    const float* state_w = (const float*)d_in[4];
    const float* Wo = (const float*)d_in[5];
    float* out = (float*)d_out;

    float* xp = nullptr;
    __nv_bfloat16 *xh, *xl, *hsh, *hsl, *WiTh, *WiTl, *WoTh, *WoTl;
    cudaGetSymbolAddress((void**)&xp, g_xp);
    cudaGetSymbolAddress((void**)&xh, g_xh);
    cudaGetSymbolAddress((void**)&xl, g_xl);
    cudaGetSymbolAddress((void**)&hsh, g_hsh);
    cudaGetSymbolAddress((void**)&hsl, g_hsl);
    cudaGetSymbolAddress((void**)&WiTh, g_WiTh);
    cudaGetSymbolAddress((void**)&WiTl, g_WiTl);
    cudaGetSymbolAddress((void**)&WoTh, g_WoTh);
    cudaGetSymbolAddress((void**)&WoTl, g_WoTl);

    cudaFuncSetAttribute(gemm_bf3<true>,
                         cudaFuncAttributeMaxDynamicSharedMemorySize, SMEMB);
    cudaFuncSetAttribute(gemm_bf3<false>,
                         cudaFuncAttributeMaxDynamicSharedMemorySize, SMEMB);

    const size_t out_elems = (size_t)BB * SS * DD;
    float* state_out = nullptr;
    if ((size_t)out_size >= out_elems + (size_t)BB * DD)
        state_out = out + out_elems;

    // 0) operand preparation
    split_f32<<<(BB * SS * DD) / 4 / 256, 256>>>(
        (const float4*)x, (__nv_bfloat162*)xh, (__nv_bfloat162*)xl);
    dim3 tgrid(DD / 32, DD / 32), tblk(32, 8);
    transpose_split<<<tgrid, tblk>>>(Wi, WiTh, WiTl);
    transpose_split<<<tgrid, tblk>>>(Wo, WoTh, WoTl);

    dim3 ggrid(DD / 128, (BB * SS) / 128);  // (16, 64)
    // 1) xp = x @ Wi + b
    gemm_bf3<true><<<ggrid, 256, SMEMB>>>(xh, xl, WiTh, WiTl, bias, xp);
    // 2) recurrence -> hs (bf16 hi/lo) + final state
    rnn_kernel<<<64, 256>>>(xp, input_state, state_w, hsh, hsl, state_out);
    // 3) out = hs @ Wo
    gemm_bf3<false><<<ggrid, 256, SMEMB>>>(hsh, hsl, WoTh, WoTl, nullptr, out);
}

// round 14
// speedup vs baseline: 1.3382x; 1.1002x over previous
#include <cuda_runtime.h>
#include <cuda_bf16.h>
#include <cstdint>

#define BB 4
#define SS 2048
#define DD 2048          // D_IN = D_STATE = D_OUT
#define NH 16
#define HH 128

// ------------------------- global scratch (no allocs) -----------------------
static __device__ float g_xp[(size_t)BB * SS * DD];                  // 64MB
static __device__ __nv_bfloat16 g_xh[(size_t)BB * SS * DD];          // 32MB
static __device__ __nv_bfloat16 g_xl[(size_t)BB * SS * DD];
static __device__ __nv_bfloat16 g_hsh[(size_t)BB * SS * DD];
static __device__ __nv_bfloat16 g_hsl[(size_t)BB * SS * DD];
static __device__ __nv_bfloat16 g_WiTh[(size_t)DD * DD];             // 8MB
static __device__ __nv_bfloat16 g_WiTl[(size_t)DD * DD];
static __device__ __nv_bfloat16 g_WoTh[(size_t)DD * DD];
static __device__ __nv_bfloat16 g_WoTl[(size_t)DD * DD];

typedef unsigned long long ull;

__device__ __forceinline__ ull pack2(float x, float y) {
    ull r; asm("mov.b64 %0, {%1,%2};" : "=l"(r) : "f"(x), "f"(y)); return r;
}
__device__ __forceinline__ float2 unpack2(ull v) {
    float lo, hi; asm("mov.b64 {%0,%1}, %2;" : "=f"(lo), "=f"(hi) : "l"(v));
    return make_float2(lo, hi);
}
__device__ __forceinline__ void fma2(ull& c, ull a, ull b) {
    asm("fma.rn.f32x2 %0, %1, %2, %3;" : "=l"(c) : "l"(a), "l"(b), "l"(c));
}

__device__ __forceinline__ uint32_t smem_u32(const void* p) {
    uint32_t a;
    asm("{ .reg .u64 t; cvta.to.shared.u64 t, %1; cvt.u32.u64 %0, t; }"
        : "=r"(a) : "l"(p));
    return a;
}
__device__ __forceinline__ void cp16(uint32_t s, const void* g) {
    asm volatile("cp.async.cg.shared.global [%0], [%1], 16;"
                 :: "r"(s), "l"(g) : "memory");
}
__device__ __forceinline__ void ldmx4(uint32_t* r, uint32_t addr) {
    asm volatile("ldmatrix.sync.aligned.m8n8.x4.shared.b16 {%0,%1,%2,%3}, [%4];"
                 : "=r"(r[0]), "=r"(r[1]), "=r"(r[2]), "=r"(r[3]) : "r"(addr));
}
__device__ __forceinline__ void mma_bf(float* c, const uint32_t* a,
                                       const uint32_t* b) {
    asm volatile(
        "mma.sync.aligned.m16n8k16.row.col.f32.bf16.bf16.f32 "
        "{%0,%1,%2,%3}, {%4,%5,%6,%7}, {%8,%9}, {%0,%1,%2,%3};"
        : "+f"(c[0]), "+f"(c[1]), "+f"(c[2]), "+f"(c[3])
        : "r"(a[0]), "r"(a[1]), "r"(a[2]), "r"(a[3]), "r"(b[0]), "r"(b[1]));
}

// ---------------------------------------------------------------------------
// elementwise split fp32 -> bf16 (hi, lo)
// ---------------------------------------------------------------------------
__global__ void __launch_bounds__(256)
split_f32(const float4* __restrict__ in, __nv_bfloat162* __restrict__ hi,
          __nv_bfloat162* __restrict__ lo) {
    int i = blockIdx.x * 256 + threadIdx.x;
    float4 v = in[i];
    __nv_bfloat16 h0 = __float2bfloat16(v.x), h1 = __float2bfloat16(v.y);
    __nv_bfloat16 h2 = __float2bfloat16(v.z), h3 = __float2bfloat16(v.w);
    hi[2 * i + 0] = __halves2bfloat162(h0, h1);
    hi[2 * i + 1] = __halves2bfloat162(h2, h3);
    lo[2 * i + 0] = __halves2bfloat162(
        __float2bfloat16(v.x - __bfloat162float(h0)),
        __float2bfloat16(v.y - __bfloat162float(h1)));
    lo[2 * i + 1] = __halves2bfloat162(
        __float2bfloat16(v.z - __bfloat162float(h2)),
        __float2bfloat16(v.w - __bfloat162float(h3)));
}

// ---------------------------------------------------------------------------
// transpose 2048x2048 fp32 + split -> bf16 hi/lo (out[n][k] = in[k][n])
// ---------------------------------------------------------------------------
__global__ void __launch_bounds__(256)
transpose_split(const float* __restrict__ in, __nv_bfloat16* __restrict__ oh,
                __nv_bfloat16* __restrict__ ol) {
    __shared__ float tile[32][33];
    int x = blockIdx.x * 32 + threadIdx.x;
    int y = blockIdx.y * 32 + threadIdx.y;
#pragma unroll
    for (int i = 0; i < 32; i += 8)
        tile[threadIdx.y + i][threadIdx.x] = in[(size_t)(y + i) * DD + x];
    __syncthreads();
    x = blockIdx.y * 32 + threadIdx.x;
    y = blockIdx.x * 32 + threadIdx.y;
#pragma unroll
    for (int i = 0; i < 32; i += 8) {
        float v = tile[threadIdx.x][threadIdx.y + i];
        __nv_bfloat16 h = __float2bfloat16(v);
        oh[(size_t)(y + i) * DD + x] = h;
        ol[(size_t)(y + i) * DD + x] =
            __float2bfloat16(v - __bfloat162float(h));
    }
}

// ---------------------------------------------------------------------------
// 3x bf16-split GEMM (round-5 config, proven 611-639us/GEMM):
//   128x128 CTA tile, K_tile 32, 8 warps (4m x 2n, warp = 32x64),
//   2-stage cp.async, 2 CTAs/SM.
// ---------------------------------------------------------------------------
#define KT 32
#define PADK 40                         // smem row stride in bf16 elems (80B)
#define OPB (128 * PADK * 2)            // 10240 B per operand tile
#define STAGEB (4 * OPB)                // 40960 B
#define SMEMB (2 * STAGEB)              // 81920 B

template <bool BIAS>
__global__ void __launch_bounds__(256, 2)
gemm_bf3(const __nv_bfloat16* __restrict__ Ah,
         const __nv_bfloat16* __restrict__ Al,
         const __nv_bfloat16* __restrict__ Bh,
         const __nv_bfloat16* __restrict__ Bl,
         const float* __restrict__ bias, float* __restrict__ C) {
    extern __shared__ __align__(128) char smem[];
    const uint32_t sb = smem_u32(smem);
    const int tid = threadIdx.x;
    const int lane = tid & 31;
    const int wid = tid >> 5;
    const int wm = wid & 3;             // 4 m-blocks of 32 rows
    const int wn = wid >> 2;            // 2 n-blocks of 64 cols
    const size_t bm = (size_t)blockIdx.y * 128;
    const size_t bn = (size_t)blockIdx.x * 128;

    // per-thread cp.async mapping: 2 16B chunks per operand
    const __nv_bfloat16* gsrc[4][2];
    uint32_t sdst[4][2];
    {
        const __nv_bfloat16* bases[4] = {Ah, Al, Bh, Bl};
#pragma unroll
        for (int op = 0; op < 4; op++)
#pragma unroll
            for (int i = 0; i < 2; i++) {
                int idx = tid * 2 + i;
                int r = idx >> 2, c = idx & 3;
                size_t grow = (op < 2 ? bm : bn) + r;
                gsrc[op][i] = bases[op] + grow * DD + c * 8;
                sdst[op][i] = sb + op * OPB + r * (PADK * 2) + c * 16;
            }
    }

    // fragment smem addresses
    const uint32_t aAddr = sb + (wm * 32 + (lane & 15)) * (PADK * 2) +
                           (lane >> 4) * 16;
    const int n_off = (lane & 7) + ((lane >> 4) & 1) * 8;
    const int k_off = ((lane >> 3) & 1) * 16;
    const uint32_t bAddr = sb + 2 * OPB + (wn * 64 + n_off) * (PADK * 2) + k_off;

    float acc[64];
#pragma unroll
    for (int i = 0; i < 64; i++) acc[i] = 0.0f;

    // prologue: stage 0 <- k-tile 0
#pragma unroll
    for (int op = 0; op < 4; op++)
#pragma unroll
        for (int i = 0; i < 2; i++)
            cp16(sdst[op][i], gsrc[op][i]);
    asm volatile("cp.async.commit_group;" ::: "memory");

    const int ntiles = DD / KT;  // 64
    for (int t = 0; t < ntiles; t++) {
        asm volatile("cp.async.wait_group 0;" ::: "memory");
        __syncthreads();

        if (t + 1 < ntiles) {
            const uint32_t so = ((t + 1) & 1) * STAGEB;
            const int ko = (t + 1) * KT;
#pragma unroll
            for (int op = 0; op < 4; op++)
#pragma unroll
                for (int i = 0; i < 2; i++)
                    cp16(sdst[op][i] + so, gsrc[op][i] + ko);
            asm volatile("cp.async.commit_group;" ::: "memory");
        }

        const uint32_t so = (t & 1) * STAGEB;
#pragma unroll
        for (int kk = 0; kk < 2; kk++) {
            uint32_t ah[2][4], al[2][4];
            ldmx4(ah[0], aAddr + so + kk * 32);
            ldmx4(ah[1], aAddr + so + 16 * (PADK * 2) + kk * 32);
            ldmx4(al[0], aAddr + so + OPB + kk * 32);
            ldmx4(al[1], aAddr + so + OPB + 16 * (PADK * 2) + kk * 32);
#pragma unroll
            for (int p = 0; p < 4; p++) {
                uint32_t bh[4], bl[4];
                ldmx4(bh, bAddr + so + p * 16 * (PADK * 2) + kk * 32);
                ldmx4(bl, bAddr + so + OPB + p * 16 * (PADK * 2) + kk * 32);
#pragma unroll
                for (int mt = 0; mt < 2; mt++) {
                    float* c0 = &acc[(mt * 8 + 2 * p) * 4];
                    float* c1 = &acc[(mt * 8 + 2 * p + 1) * 4];
                    mma_bf(c0, ah[mt], bh + 0);
                    mma_bf(c1, ah[mt], bh + 2);
                    mma_bf(c0, al[mt], bh + 0);
                    mma_bf(c1, al[mt], bh + 2);
                    mma_bf(c0, ah[mt], bl + 0);
                    mma_bf(c1, ah[mt], bl + 2);
                }
            }
        }
        __syncthreads();
    }

    // epilogue
#pragma unroll
    for (int mt = 0; mt < 2; mt++) {
        const size_t r0 = bm + wm * 32 + mt * 16 + (lane >> 2);
#pragma unroll
        for (int nt = 0; nt < 8; nt++) {
            const size_t col = bn + wn * 64 + nt * 8 + (lane & 3) * 2;
            const float* a = &acc[(mt * 8 + nt) * 4];
            float2 v0 = make_float2(a[0], a[1]);
            float2 v1 = make_float2(a[2], a[3]);
            if (BIAS) {
                float2 bv = *(const float2*)&bias[col];
                v0.x += bv.x; v0.y += bv.y;
                v1.x += bv.x; v1.y += bv.y;
            }
            *(float2*)&C[r0 * DD + col] = v0;
            *(float2*)&C[(r0 + 8) * DD + col] = v1;
        }
    }
}

// ---------------------------------------------------------------------------
// Recurrence v3: 64 CTAs x 256 threads, pair-split dot products (as v2),
// time loop unrolled 8x so the xp prefetch ring lives in REGISTERS
// (v2's xq[t&7] dynamic indexing forced it into local memory -> LDL/STL on
// the critical path every step).
// ---------------------------------------------------------------------------
__global__ void __launch_bounds__(256, 1)
rnn_kernel(const float* __restrict__ xp, const float* __restrict__ init_state,
           const float* __restrict__ state_w,
           __nv_bfloat16* __restrict__ hs_h, __nv_bfloat16* __restrict__ hs_l,
           float* __restrict__ out_state) {
    const int b = blockIdx.x >> 4;
    const int n = blockIdx.x & 15;
    const int tid = threadIdx.x;
    const int j = tid >> 1;             // output column 0..127
    const int half = tid & 1;           // row half: 0 -> rows 0..63, 1 -> 64..127

    __shared__ __align__(16) float h_sh[2][HH];

    // W[n] column j, rows half*64 .. half*64+63, as 32 packed pairs
    ull w2[32];
    const float* W = state_w + (size_t)n * HH * HH + half * 64 * HH + j;
#pragma unroll
    for (int m = 0; m < 32; m++)
        w2[m] = pack2(W[(2 * m) * HH], W[(2 * m + 1) * HH]);

    if (half == 0) h_sh[0][j] = init_state[b * DD + n * HH + j];

    const float* xb = xp + ((size_t)b * SS * NH + n) * HH + j;  // stride DD
    __nv_bfloat16* hbh = hs_h + ((size_t)b * SS * NH + n) * HH + j;
    __nv_bfloat16* hbl = hs_l + ((size_t)b * SS * NH + n) * HH + j;

    float xq[8];
#pragma unroll
    for (int p = 0; p < 8; p++) xq[p] = xb[(size_t)p * DD];

    __syncthreads();

    int cur = 0;
    for (int t0 = 0; t0 < SS; t0 += 8) {
#pragma unroll
        for (int u = 0; u < 8; u++) {
            const int t = t0 + u;
            // this half's 64 h values = 16 LDS.128 (broadcast across pairs)
            const ulonglong2* hv = (const ulonglong2*)&h_sh[cur][half * 64];
            ull a0 = 0ull, a1 = 0ull, a2 = 0ull, a3 = 0ull;
#pragma unroll
            for (int q = 0; q < 16; q += 4) {
                ulonglong2 h0 = hv[q + 0];
                ulonglong2 h1 = hv[q + 1];
                ulonglong2 h2 = hv[q + 2];
                ulonglong2 h3 = hv[q + 3];
                fma2(a0, h0.x, w2[2 * q + 0]);
                fma2(a1, h0.y, w2[2 * q + 1]);
                fma2(a2, h1.x, w2[2 * q + 2]);
                fma2(a3, h1.y, w2[2 * q + 3]);
                fma2(a0, h2.x, w2[2 * q + 4]);
                fma2(a1, h2.y, w2[2 * q + 5]);
                fma2(a2, h3.x, w2[2 * q + 6]);
                fma2(a3, h3.y, w2[2 * q + 7]);
            }
            float2 f0 = unpack2(a0), f1 = unpack2(a1);
            float2 f2 = unpack2(a2), f3 = unpack2(a3);
            float s = ((f0.x + f0.y) + (f1.x + f1.y)) +
                      ((f2.x + f2.y) + (f3.x + f3.y));
            // combine the two halves (lanes 2k <-> 2k+1)
            s += __shfl_xor_sync(0xFFFFFFFFu, s, 1);

            const float xv = xq[u];                      // static index
            if (t + 8 < SS) xq[u] = xb[(size_t)(t + 8) * DD];

            const float hn = tanhf(s + xv);
            // release the barrier-gating value FIRST
            if (half == 0) h_sh[cur ^ 1][j] = hn;
            const __nv_bfloat16 hh = __float2bfloat16(hn);
            if (half == 0) {
                hbh[(size_t)t * DD] = hh;
            } else {
                hbl[(size_t)t * DD] =
                    __float2bfloat16(hn - __bfloat162float(hh));
            }
            __syncthreads();
            cur ^= 1;
        }
    }

    if (out_state && half == 0)
        out_state[b * DD + n * HH + j] = h_sh[cur][j];
}

// ---------------------------------------------------------------------------
extern "C" void kernel_launch(void* const* d_in, const int* in_sizes, int n_in,
                              void* d_out, int out_size) {
    const float* x = (const float*)d_in[0];
    const float* input_state = (const float*)d_in[1];
    const float* Wi = (const float*)d_in[2];
    const float* bias = (const float*)d_in[3];
    const float* state_w = (const float*)d_in[4];
    const float* Wo = (const float*)d_in[5];
    float* out = (float*)d_out;

    float* xp = nullptr;
    __nv_bfloat16 *xh, *xl, *hsh, *hsl, *WiTh, *WiTl, *WoTh, *WoTl;
    cudaGetSymbolAddress((void**)&xp, g_xp);
    cudaGetSymbolAddress((void**)&xh, g_xh);
    cudaGetSymbolAddress((void**)&xl, g_xl);
    cudaGetSymbolAddress((void**)&hsh, g_hsh);
    cudaGetSymbolAddress((void**)&hsl, g_hsl);
    cudaGetSymbolAddress((void**)&WiTh, g_WiTh);
    cudaGetSymbolAddress((void**)&WiTl, g_WiTl);
    cudaGetSymbolAddress((void**)&WoTh, g_WoTh);
    cudaGetSymbolAddress((void**)&WoTl, g_WoTl);

    cudaFuncSetAttribute(gemm_bf3<true>,
                         cudaFuncAttributeMaxDynamicSharedMemorySize, SMEMB);
    cudaFuncSetAttribute(gemm_bf3<false>,
                         cudaFuncAttributeMaxDynamicSharedMemorySize, SMEMB);

    const size_t out_elems = (size_t)BB * SS * DD;
    float* state_out = nullptr;
    if ((size_t)out_size >= out_elems + (size_t)BB * DD)
        state_out = out + out_elems;

    // 0) operand preparation
    split_f32<<<(BB * SS * DD) / 4 / 256, 256>>>(
        (const float4*)x, (__nv_bfloat162*)xh, (__nv_bfloat162*)xl);
    dim3 tgrid(DD / 32, DD / 32), tblk(32, 8);
    transpose_split<<<tgrid, tblk>>>(Wi, WiTh, WiTl);
    transpose_split<<<tgrid, tblk>>>(Wo, WoTh, WoTl);

    dim3 ggrid(DD / 128, (BB * SS) / 128);  // (16, 64)
    // 1) xp = x @ Wi + b
    gemm_bf3<true><<<ggrid, 256, SMEMB>>>(xh, xl, WiTh, WiTl, bias, xp);
    // 2) recurrence -> hs (bf16 hi/lo) + final state
    rnn_kernel<<<64, 256>>>(xp, input_state, state_w, hsh, hsl, state_out);
    // 3) out = hs @ Wo
    gemm_bf3<false><<<ggrid, 256, SMEMB>>>(hsh, hsl, WoTh, WoTl, nullptr, out);
}

// round 15
// speedup vs baseline: 1.4327x; 1.0706x over previous
#include <cuda_runtime.h>
#include <cuda_bf16.h>
#include <cstdint>

#define BB 4
#define SS 2048
#define DD 2048          // D_IN = D_STATE = D_OUT
#define NH 16
#define HH 128

// ------------------------- global scratch (no allocs) -----------------------
static __device__ float g_xp[(size_t)BB * SS * DD];                  // 64MB
static __device__ __nv_bfloat16 g_xh[(size_t)BB * SS * DD];          // 32MB
static __device__ __nv_bfloat16 g_xl[(size_t)BB * SS * DD];
static __device__ __nv_bfloat16 g_hsh[(size_t)BB * SS * DD];
static __device__ __nv_bfloat16 g_hsl[(size_t)BB * SS * DD];
static __device__ __nv_bfloat16 g_WiTh[(size_t)DD * DD];             // 8MB
static __device__ __nv_bfloat16 g_WiTl[(size_t)DD * DD];
static __device__ __nv_bfloat16 g_WoTh[(size_t)DD * DD];
static __device__ __nv_bfloat16 g_WoTl[(size_t)DD * DD];

typedef unsigned long long ull;

__device__ __forceinline__ ull pack2(float x, float y) {
    ull r; asm("mov.b64 %0, {%1,%2};" : "=l"(r) : "f"(x), "f"(y)); return r;
}
__device__ __forceinline__ float2 unpack2(ull v) {
    float lo, hi; asm("mov.b64 {%0,%1}, %2;" : "=f"(lo), "=f"(hi) : "l"(v));
    return make_float2(lo, hi);
}
__device__ __forceinline__ void fma2(ull& c, ull a, ull b) {
    asm("fma.rn.f32x2 %0, %1, %2, %3;" : "=l"(c) : "l"(a), "l"(b), "l"(c));
}

__device__ __forceinline__ uint32_t smem_u32(const void* p) {
    uint32_t a;
    asm("{ .reg .u64 t; cvta.to.shared.u64 t, %1; cvt.u32.u64 %0, t; }"
        : "=r"(a) : "l"(p));
    return a;
}
__device__ __forceinline__ void cp16(uint32_t s, const void* g) {
    asm volatile("cp.async.cg.shared.global [%0], [%1], 16;"
                 :: "r"(s), "l"(g) : "memory");
}
__device__ __forceinline__ void ldmx4(uint32_t* r, uint32_t addr) {
    asm volatile("ldmatrix.sync.aligned.m8n8.x4.shared.b16 {%0,%1,%2,%3}, [%4];"
                 : "=r"(r[0]), "=r"(r[1]), "=r"(r[2]), "=r"(r[3]) : "r"(addr));
}
__device__ __forceinline__ void mma_bf(float* c, const uint32_t* a,
                                       const uint32_t* b) {
    asm volatile(
        "mma.sync.aligned.m16n8k16.row.col.f32.bf16.bf16.f32 "
        "{%0,%1,%2,%3}, {%4,%5,%6,%7}, {%8,%9}, {%0,%1,%2,%3};"
        : "+f"(c[0]), "+f"(c[1]), "+f"(c[2]), "+f"(c[3])
        : "r"(a[0]), "r"(a[1]), "r"(a[2]), "r"(a[3]), "r"(b[0]), "r"(b[1]));
}

// branch-free fp32 tanh: clamp, ex2.approx, rcp.approx + 1 Newton.
// |err| <= ~1e-7 absolute over the whole range (tanh(15) == 1.0f in fp32).
__device__ __forceinline__ float fast_tanh(float x) {
    float xa = fminf(fmaxf(x, -15.0f), 15.0f);
    float e;
    asm("ex2.approx.f32 %0, %1;" : "=f"(e) : "f"(xa * 2.8853900817779268f));
    float num = e - 1.0f;
    float den = e + 1.0f;
    float r;
    asm("rcp.approx.f32 %0, %1;" : "=f"(r) : "f"(den));
    r = r * (2.0f - den * r);          // Newton: err ~2^-29
    return num * r;
}

// ---------------------------------------------------------------------------
// elementwise split fp32 -> bf16 (hi, lo)
// ---------------------------------------------------------------------------
__global__ void __launch_bounds__(256)
split_f32(const float4* __restrict__ in, __nv_bfloat162* __restrict__ hi,
          __nv_bfloat162* __restrict__ lo) {
    int i = blockIdx.x * 256 + threadIdx.x;
    float4 v = in[i];
    __nv_bfloat16 h0 = __float2bfloat16(v.x), h1 = __float2bfloat16(v.y);
    __nv_bfloat16 h2 = __float2bfloat16(v.z), h3 = __float2bfloat16(v.w);
    hi[2 * i + 0] = __halves2bfloat162(h0, h1);
    hi[2 * i + 1] = __halves2bfloat162(h2, h3);
    lo[2 * i + 0] = __halves2bfloat162(
        __float2bfloat16(v.x - __bfloat162float(h0)),
        __float2bfloat16(v.y - __bfloat162float(h1)));
    lo[2 * i + 1] = __halves2bfloat162(
        __float2bfloat16(v.z - __bfloat162float(h2)),
        __float2bfloat16(v.w - __bfloat162float(h3)));
}

// ---------------------------------------------------------------------------
// transpose 2048x2048 fp32 + split -> bf16 hi/lo (out[n][k] = in[k][n])
// ---------------------------------------------------------------------------
__global__ void __launch_bounds__(256)
transpose_split(const float* __restrict__ in, __nv_bfloat16* __restrict__ oh,
                __nv_bfloat16* __restrict__ ol) {
    __shared__ float tile[32][33];
    int x = blockIdx.x * 32 + threadIdx.x;
    int y = blockIdx.y * 32 + threadIdx.y;
#pragma unroll
    for (int i = 0; i < 32; i += 8)
        tile[threadIdx.y + i][threadIdx.x] = in[(size_t)(y + i) * DD + x];
    __syncthreads();
    x = blockIdx.y * 32 + threadIdx.x;
    y = blockIdx.x * 32 + threadIdx.y;
#pragma unroll
    for (int i = 0; i < 32; i += 8) {
        float v = tile[threadIdx.x][threadIdx.y + i];
        __nv_bfloat16 h = __float2bfloat16(v);
        oh[(size_t)(y + i) * DD + x] = h;
        ol[(size_t)(y + i) * DD + x] =
            __float2bfloat16(v - __bfloat162float(h));
    }
}

// ---------------------------------------------------------------------------
// 3x bf16-split GEMM (round-5 config, proven 611-639us/GEMM):
//   128x128 CTA tile, K_tile 32, 8 warps (4m x 2n, warp = 32x64),
//   2-stage cp.async, 2 CTAs/SM.
// ---------------------------------------------------------------------------
#define KT 32
#define PADK 40                         // smem row stride in bf16 elems (80B)
#define OPB (128 * PADK * 2)            // 10240 B per operand tile
#define STAGEB (4 * OPB)                // 40960 B
#define SMEMB (2 * STAGEB)              // 81920 B

template <bool BIAS>
__global__ void __launch_bounds__(256, 2)
gemm_bf3(const __nv_bfloat16* __restrict__ Ah,
         const __nv_bfloat16* __restrict__ Al,
         const __nv_bfloat16* __restrict__ Bh,
         const __nv_bfloat16* __restrict__ Bl,
         const float* __restrict__ bias, float* __restrict__ C) {
    extern __shared__ __align__(128) char smem[];
    const uint32_t sb = smem_u32(smem);
    const int tid = threadIdx.x;
    const int lane = tid & 31;
    const int wid = tid >> 5;
    const int wm = wid & 3;             // 4 m-blocks of 32 rows
    const int wn = wid >> 2;            // 2 n-blocks of 64 cols
    const size_t bm = (size_t)blockIdx.y * 128;
    const size_t bn = (size_t)blockIdx.x * 128;

    // per-thread cp.async mapping: 2 16B chunks per operand
    const __nv_bfloat16* gsrc[4][2];
    uint32_t sdst[4][2];
    {
        const __nv_bfloat16* bases[4] = {Ah, Al, Bh, Bl};
#pragma unroll
        for (int op = 0; op < 4; op++)
#pragma unroll
            for (int i = 0; i < 2; i++) {
                int idx = tid * 2 + i;
                int r = idx >> 2, c = idx & 3;
                size_t grow = (op < 2 ? bm : bn) + r;
                gsrc[op][i] = bases[op] + grow * DD + c * 8;
                sdst[op][i] = sb + op * OPB + r * (PADK * 2) + c * 16;
            }
    }

    // fragment smem addresses
    const uint32_t aAddr = sb + (wm * 32 + (lane & 15)) * (PADK * 2) +
                           (lane >> 4) * 16;
    const int n_off = (lane & 7) + ((lane >> 4) & 1) * 8;
    const int k_off = ((lane >> 3) & 1) * 16;
    const uint32_t bAddr = sb + 2 * OPB + (wn * 64 + n_off) * (PADK * 2) + k_off;

    float acc[64];
#pragma unroll
    for (int i = 0; i < 64; i++) acc[i] = 0.0f;

    // prologue: stage 0 <- k-tile 0
#pragma unroll
    for (int op = 0; op < 4; op++)
#pragma unroll
        for (int i = 0; i < 2; i++)
            cp16(sdst[op][i], gsrc[op][i]);
    asm volatile("cp.async.commit_group;" ::: "memory");

    const int ntiles = DD / KT;  // 64
    for (int t = 0; t < ntiles; t++) {
        asm volatile("cp.async.wait_group 0;" ::: "memory");
        __syncthreads();

        if (t + 1 < ntiles) {
            const uint32_t so = ((t + 1) & 1) * STAGEB;
            const int ko = (t + 1) * KT;
#pragma unroll
            for (int op = 0; op < 4; op++)
#pragma unroll
                for (int i = 0; i < 2; i++)
                    cp16(sdst[op][i] + so, gsrc[op][i] + ko);
            asm volatile("cp.async.commit_group;" ::: "memory");
        }

        const uint32_t so = (t & 1) * STAGEB;
#pragma unroll
        for (int kk = 0; kk < 2; kk++) {
            uint32_t ah[2][4], al[2][4];
            ldmx4(ah[0], aAddr + so + kk * 32);
            ldmx4(ah[1], aAddr + so + 16 * (PADK * 2) + kk * 32);
            ldmx4(al[0], aAddr + so + OPB + kk * 32);
            ldmx4(al[1], aAddr + so + OPB + 16 * (PADK * 2) + kk * 32);
#pragma unroll
            for (int p = 0; p < 4; p++) {
                uint32_t bh[4], bl[4];
                ldmx4(bh, bAddr + so + p * 16 * (PADK * 2) + kk * 32);
                ldmx4(bl, bAddr + so + OPB + p * 16 * (PADK * 2) + kk * 32);
#pragma unroll
                for (int mt = 0; mt < 2; mt++) {
                    float* c0 = &acc[(mt * 8 + 2 * p) * 4];
                    float* c1 = &acc[(mt * 8 + 2 * p + 1) * 4];
                    mma_bf(c0, ah[mt], bh + 0);
                    mma_bf(c1, ah[mt], bh + 2);
                    mma_bf(c0, al[mt], bh + 0);
                    mma_bf(c1, al[mt], bh + 2);
                    mma_bf(c0, ah[mt], bl + 0);
                    mma_bf(c1, ah[mt], bl + 2);
                }
            }
        }
        __syncthreads();
    }

    // epilogue
#pragma unroll
    for (int mt = 0; mt < 2; mt++) {
        const size_t r0 = bm + wm * 32 + mt * 16 + (lane >> 2);
#pragma unroll
        for (int nt = 0; nt < 8; nt++) {
            const size_t col = bn + wn * 64 + nt * 8 + (lane & 3) * 2;
            const float* a = &acc[(mt * 8 + nt) * 4];
            float2 v0 = make_float2(a[0], a[1]);
            float2 v1 = make_float2(a[2], a[3]);
            if (BIAS) {
                float2 bv = *(const float2*)&bias[col];
                v0.x += bv.x; v0.y += bv.y;
                v1.x += bv.x; v1.y += bv.y;
            }
            *(float2*)&C[r0 * DD + col] = v0;
            *(float2*)&C[(r0 + 8) * DD + col] = v1;
        }
    }
}

// ---------------------------------------------------------------------------
// Recurrence v4: v3 (pair-split, 8x-unrolled register ring) plus:
//   - fast_tanh (branch-free ex2/rcp, ~60-cyc chain vs libm tanhf)
//   - padded h_sh layout: half1 at +4 floats -> the two LDS.128 addresses per
//     warp hit DISJOINT bank groups (was a 2-way conflict on every load)
//   - xq prefetch issued at the top of the step (independent of the chain)
// ---------------------------------------------------------------------------
#define HP 136                          // padded row: 64 | pad 4 | 64 | pad 4
__global__ void __launch_bounds__(256, 1)
rnn_kernel(const float* __restrict__ xp, const float* __restrict__ init_state,
           const float* __restrict__ state_w,
           __nv_bfloat16* __restrict__ hs_h, __nv_bfloat16* __restrict__ hs_l,
           float* __restrict__ out_state) {
    const int b = blockIdx.x >> 4;
    const int n = blockIdx.x & 15;
    const int tid = threadIdx.x;
    const int j = tid >> 1;             // output column 0..127
    const int half = tid & 1;           // row half: 0 -> rows 0..63, 1 -> 64..127

    __shared__ __align__(16) float h_sh[2][HP];

    // W[n] column j, rows half*64 .. half*64+63, as 32 packed pairs
    ull w2[32];
    const float* W = state_w + (size_t)n * HH * HH + half * 64 * HH + j;
#pragma unroll
    for (int m = 0; m < 32; m++)
        w2[m] = pack2(W[(2 * m) * HH], W[(2 * m + 1) * HH]);

    const int jpos = j + ((j >> 6) << 2);          // padded position of col j
    if (half == 0) h_sh[0][jpos] = init_state[b * DD + n * HH + j];

    const float* xb = xp + ((size_t)b * SS * NH + n) * HH + j;  // stride DD
    __nv_bfloat16* hbh = hs_h + ((size_t)b * SS * NH + n) * HH + j;
    __nv_bfloat16* hbl = hs_l + ((size_t)b * SS * NH + n) * HH + j;

    float xq[8];
#pragma unroll
    for (int p = 0; p < 8; p++) xq[p] = xb[(size_t)p * DD];

    __syncthreads();

    const int hbase = half * 68;        // padded base of this half's rows
    int cur = 0;
    for (int t0 = 0; t0 < SS; t0 += 8) {
#pragma unroll
        for (int u = 0; u < 8; u++) {
            const int t = t0 + u;
            const float xv = xq[u];                      // static index
            if (t + 8 < SS) xq[u] = xb[(size_t)(t + 8) * DD];  // issue early

            // this half's 64 h values = 16 LDS.128, conflict-free
            const ulonglong2* hv = (const ulonglong2*)&h_sh[cur][hbase];
            ull a0 = 0ull, a1 = 0ull, a2 = 0ull, a3 = 0ull;
#pragma unroll
            for (int q = 0; q < 16; q += 4) {
                ulonglong2 h0 = hv[q + 0];
                ulonglong2 h1 = hv[q + 1];
                ulonglong2 h2 = hv[q + 2];
                ulonglong2 h3 = hv[q + 3];
                fma2(a0, h0.x, w2[2 * q + 0]);
                fma2(a1, h0.y, w2[2 * q + 1]);
                fma2(a2, h1.x, w2[2 * q + 2]);
                fma2(a3, h1.y, w2[2 * q + 3]);
                fma2(a0, h2.x, w2[2 * q + 4]);
                fma2(a1, h2.y, w2[2 * q + 5]);
                fma2(a2, h3.x, w2[2 * q + 6]);
                fma2(a3, h3.y, w2[2 * q + 7]);
            }
            float2 f0 = unpack2(a0), f1 = unpack2(a1);
            float2 f2 = unpack2(a2), f3 = unpack2(a3);
            float s = ((f0.x + f0.y) + (f1.x + f1.y)) +
                      ((f2.x + f2.y) + (f3.x + f3.y));
            // combine the two halves (lanes 2k <-> 2k+1)
            s += __shfl_xor_sync(0xFFFFFFFFu, s, 1);

            const float hn = fast_tanh(s + xv);
            // release the barrier-gating value FIRST
            if (half == 0) h_sh[cur ^ 1][jpos] = hn;
            const __nv_bfloat16 hh = __float2bfloat16(hn);
            if (half == 0) {
                hbh[(size_t)t * DD] = hh;
            } else {
                hbl[(size_t)t * DD] =
                    __float2bfloat16(hn - __bfloat162float(hh));
            }
            __syncthreads();
            cur ^= 1;
        }
    }

    if (out_state && half == 0)
        out_state[b * DD + n * HH + j] = h_sh[cur][jpos];
}

// ---------------------------------------------------------------------------
extern "C" void kernel_launch(void* const* d_in, const int* in_sizes, int n_in,
                              void* d_out, int out_size) {
    const float* x = (const float*)d_in[0];
    const float* input_state = (const float*)d_in[1];
    const float* Wi = (const float*)d_in[2];
    const float* bias = (const float*)d_in[3];
    const float* state_w = (const float*)d_in[4];
    const float* Wo = (const float*)d_in[5];
    float* out = (float*)d_out;

    float* xp = nullptr;
    __nv_bfloat16 *xh, *xl, *hsh, *hsl, *WiTh, *WiTl, *WoTh, *WoTl;
    cudaGetSymbolAddress((void**)&xp, g_xp);
    cudaGetSymbolAddress((void**)&xh, g_xh);
    cudaGetSymbolAddress((void**)&xl, g_xl);
    cudaGetSymbolAddress((void**)&hsh, g_hsh);
    cudaGetSymbolAddress((void**)&hsl, g_hsl);
    cudaGetSymbolAddress((void**)&WiTh, g_WiTh);
    cudaGetSymbolAddress((void**)&WiTl, g_WiTl);
    cudaGetSymbolAddress((void**)&WoTh, g_WoTh);
    cudaGetSymbolAddress((void**)&WoTl, g_WoTl);

    cudaFuncSetAttribute(gemm_bf3<true>,
                         cudaFuncAttributeMaxDynamicSharedMemorySize, SMEMB);
    cudaFuncSetAttribute(gemm_bf3<false>,
                         cudaFuncAttributeMaxDynamicSharedMemorySize, SMEMB);

    const size_t out_elems = (size_t)BB * SS * DD;
    float* state_out = nullptr;
    if ((size_t)out_size >= out_elems + (size_t)BB * DD)
        state_out = out + out_elems;

    // 0) operand preparation
    split_f32<<<(BB * SS * DD) / 4 / 256, 256>>>(
        (const float4*)x, (__nv_bfloat162*)xh, (__nv_bfloat162*)xl);
    dim3 tgrid(DD / 32, DD / 32), tblk(32, 8);
    transpose_split<<<tgrid, tblk>>>(Wi, WiTh, WiTl);
    transpose_split<<<tgrid, tblk>>>(Wo, WoTh, WoTl);

    dim3 ggrid(DD / 128, (BB * SS) / 128);  // (16, 64)
    // 1) xp = x @ Wi + b
    gemm_bf3<true><<<ggrid, 256, SMEMB>>>(xh, xl, WiTh, WiTl, bias, xp);
    // 2) recurrence -> hs (bf16 hi/lo) + final state
    rnn_kernel<<<64, 256>>>(xp, input_state, state_w, hsh, hsl, state_out);
    // 3) out = hs @ Wo
    gemm_bf3<false><<<ggrid, 256, SMEMB>>>(hsh, hsl, WoTh, WoTl, nullptr, out);
}

// round 17
// speedup vs baseline: 1.6200x; 1.1308x over previous
#include <cuda_runtime.h>
#include <cuda_bf16.h>
#include <cstdint>

#define BB 4
#define SS 2048
#define DD 2048          // D_IN = D_STATE = D_OUT
#define NH 16
#define HH 128

// ------------------------- global scratch (no allocs) -----------------------
static __device__ float g_xp[(size_t)BB * SS * DD];                  // 64MB
static __device__ __nv_bfloat16 g_xh[(size_t)BB * SS * DD];          // 32MB
static __device__ __nv_bfloat16 g_xl[(size_t)BB * SS * DD];
static __device__ __nv_bfloat16 g_hsh[(size_t)BB * SS * DD];
static __device__ __nv_bfloat16 g_hsl[(size_t)BB * SS * DD];
static __device__ __nv_bfloat16 g_WiTh[(size_t)DD * DD];             // 8MB
static __device__ __nv_bfloat16 g_WiTl[(size_t)DD * DD];
static __device__ __nv_bfloat16 g_WoTh[(size_t)DD * DD];
static __device__ __nv_bfloat16 g_WoTl[(size_t)DD * DD];
static __device__ unsigned g_cnt[BB * 16];       // rnn->G2 progress flags

typedef unsigned long long ull;

__device__ __forceinline__ ull pack2(float x, float y) {
    ull r; asm("mov.b64 %0, {%1,%2};" : "=l"(r) : "f"(x), "f"(y)); return r;
}
__device__ __forceinline__ float2 unpack2(ull v) {
    float lo, hi; asm("mov.b64 {%0,%1}, %2;" : "=f"(lo), "=f"(hi) : "l"(v));
    return make_float2(lo, hi);
}
__device__ __forceinline__ void fma2(ull& c, ull a, ull b) {
    asm("fma.rn.f32x2 %0, %1, %2, %3;" : "=l"(c) : "l"(a), "l"(b), "l"(c));
}

__device__ __forceinline__ uint32_t smem_u32(const void* p) {
    uint32_t a;
    asm("{ .reg .u64 t; cvta.to.shared.u64 t, %1; cvt.u32.u64 %0, t; }"
        : "=r"(a) : "l"(p));
    return a;
}
__device__ __forceinline__ void cp16(uint32_t s, const void* g) {
    asm volatile("cp.async.cg.shared.global [%0], [%1], 16;"
                 :: "r"(s), "l"(g) : "memory");
}
__device__ __forceinline__ void ldmx4(uint32_t* r, uint32_t addr) {
    asm volatile("ldmatrix.sync.aligned.m8n8.x4.shared.b16 {%0,%1,%2,%3}, [%4];"
                 : "=r"(r[0]), "=r"(r[1]), "=r"(r[2]), "=r"(r[3]) : "r"(addr));
}
__device__ __forceinline__ void mma_bf(float* c, const uint32_t* a,
                                       const uint32_t* b) {
    asm volatile(
        "mma.sync.aligned.m16n8k16.row.col.f32.bf16.bf16.f32 "
        "{%0,%1,%2,%3}, {%4,%5,%6,%7}, {%8,%9}, {%0,%1,%2,%3};"
        : "+f"(c[0]), "+f"(c[1]), "+f"(c[2]), "+f"(c[3])
        : "r"(a[0]), "r"(a[1]), "r"(a[2]), "r"(a[3]), "r"(b[0]), "r"(b[1]));
}

// branch-free fp32 tanh: clamp, ex2.approx, rcp.approx + 1 Newton.
__device__ __forceinline__ float fast_tanh(float x) {
    float xa = fminf(fmaxf(x, -15.0f), 15.0f);
    float e;
    asm("ex2.approx.f32 %0, %1;" : "=f"(e) : "f"(xa * 2.8853900817779268f));
    float num = e - 1.0f;
    float den = e + 1.0f;
    float r;
    asm("rcp.approx.f32 %0, %1;" : "=f"(r) : "f"(den));
    r = r * (2.0f - den * r);
    return num * r;
}

// ---------------------------------------------------------------------------
// prep kernels
// ---------------------------------------------------------------------------
__global__ void __launch_bounds__(256)
split_f32(const float4* __restrict__ in, __nv_bfloat162* __restrict__ hi,
          __nv_bfloat162* __restrict__ lo) {
    int i = blockIdx.x * 256 + threadIdx.x;
    float4 v = in[i];
    __nv_bfloat16 h0 = __float2bfloat16(v.x), h1 = __float2bfloat16(v.y);
    __nv_bfloat16 h2 = __float2bfloat16(v.z), h3 = __float2bfloat16(v.w);
    hi[2 * i + 0] = __halves2bfloat162(h0, h1);
    hi[2 * i + 1] = __halves2bfloat162(h2, h3);
    lo[2 * i + 0] = __halves2bfloat162(
        __float2bfloat16(v.x - __bfloat162float(h0)),
        __float2bfloat16(v.y - __bfloat162float(h1)));
    lo[2 * i + 1] = __halves2bfloat162(
        __float2bfloat16(v.z - __bfloat162float(h2)),
        __float2bfloat16(v.w - __bfloat162float(h3)));
}

__global__ void __launch_bounds__(256)
transpose_split(const float* __restrict__ in, __nv_bfloat16* __restrict__ oh,
                __nv_bfloat16* __restrict__ ol) {
    __shared__ float tile[32][33];
    int x = blockIdx.x * 32 + threadIdx.x;
    int y = blockIdx.y * 32 + threadIdx.y;
#pragma unroll
    for (int i = 0; i < 32; i += 8)
        tile[threadIdx.y + i][threadIdx.x] = in[(size_t)(y + i) * DD + x];
    __syncthreads();
    x = blockIdx.y * 32 + threadIdx.x;
    y = blockIdx.x * 32 + threadIdx.y;
#pragma unroll
    for (int i = 0; i < 32; i += 8) {
        float v = tile[threadIdx.x][threadIdx.y + i];
        __nv_bfloat16 h = __float2bfloat16(v);
        oh[(size_t)(y + i) * DD + x] = h;
        ol[(size_t)(y + i) * DD + x] =
            __float2bfloat16(v - __bfloat162float(h));
    }
}

__global__ void cnt_reset() { g_cnt[threadIdx.x] = 0u; }

// ---------------------------------------------------------------------------
// 3x bf16-split GEMM tile (proven round-5 config) as a device function.
// CTA tile 128x128, K_tile 32, 8 warps (4m x 2n), 2-stage cp.async.
// ---------------------------------------------------------------------------
#define KT 32
#define PADK 40
#define OPB (128 * PADK * 2)            // 10240 B per operand tile
#define STAGEB (4 * OPB)                // 40960 B
#define SMEMB (2 * STAGEB)              // 81920 B

template <bool BIAS>
__device__ __forceinline__ void gemm_tile(
    const __nv_bfloat16* __restrict__ Ah,
    const __nv_bfloat16* __restrict__ Al,
    const __nv_bfloat16* __restrict__ Bh,
    const __nv_bfloat16* __restrict__ Bl,
    const float* __restrict__ bias, float* __restrict__ C,
    size_t bm, size_t bn, char* smem) {
    const uint32_t sb = smem_u32(smem);
    const int tid = threadIdx.x;
    const int lane = tid & 31;
    const int wid = tid >> 5;
    const int wm = wid & 3;
    const int wn = wid >> 2;

    const __nv_bfloat16* gsrc[4][2];
    uint32_t sdst[4][2];
    {
        const __nv_bfloat16* bases[4] = {Ah, Al, Bh, Bl};
#pragma unroll
        for (int op = 0; op < 4; op++)
#pragma unroll
            for (int i = 0; i < 2; i++) {
                int idx = tid * 2 + i;
                int r = idx >> 2, c = idx & 3;
                size_t grow = (op < 2 ? bm : bn) + r;
                gsrc[op][i] = bases[op] + grow * DD + c * 8;
                sdst[op][i] = sb + op * OPB + r * (PADK * 2) + c * 16;
            }
    }

    const uint32_t aAddr = sb + (wm * 32 + (lane & 15)) * (PADK * 2) +
                           (lane >> 4) * 16;
    const int n_off = (lane & 7) + ((lane >> 4) & 1) * 8;
    const int k_off = ((lane >> 3) & 1) * 16;
    const uint32_t bAddr = sb + 2 * OPB + (wn * 64 + n_off) * (PADK * 2) + k_off;

    float acc[64];
#pragma unroll
    for (int i = 0; i < 64; i++) acc[i] = 0.0f;

#pragma unroll
    for (int op = 0; op < 4; op++)
#pragma unroll
        for (int i = 0; i < 2; i++)
            cp16(sdst[op][i], gsrc[op][i]);
    asm volatile("cp.async.commit_group;" ::: "memory");

    const int ntiles = DD / KT;  // 64
    for (int t = 0; t < ntiles; t++) {
        asm volatile("cp.async.wait_group 0;" ::: "memory");
        __syncthreads();

        if (t + 1 < ntiles) {
            const uint32_t so = ((t + 1) & 1) * STAGEB;
            const int ko = (t + 1) * KT;
#pragma unroll
            for (int op = 0; op < 4; op++)
#pragma unroll
                for (int i = 0; i < 2; i++)
                    cp16(sdst[op][i] + so, gsrc[op][i] + ko);
            asm volatile("cp.async.commit_group;" ::: "memory");
        }

        const uint32_t so = (t & 1) * STAGEB;
#pragma unroll
        for (int kk = 0; kk < 2; kk++) {
            uint32_t ah[2][4], al[2][4];
            ldmx4(ah[0], aAddr + so + kk * 32);
            ldmx4(ah[1], aAddr + so + 16 * (PADK * 2) + kk * 32);
            ldmx4(al[0], aAddr + so + OPB + kk * 32);
            ldmx4(al[1], aAddr + so + OPB + 16 * (PADK * 2) + kk * 32);
#pragma unroll
            for (int p = 0; p < 4; p++) {
                uint32_t bh[4], bl[4];
                ldmx4(bh, bAddr + so + p * 16 * (PADK * 2) + kk * 32);
                ldmx4(bl, bAddr + so + OPB + p * 16 * (PADK * 2) + kk * 32);
#pragma unroll
                for (int mt = 0; mt < 2; mt++) {
                    float* c0 = &acc[(mt * 8 + 2 * p) * 4];
                    float* c1 = &acc[(mt * 8 + 2 * p + 1) * 4];
                    mma_bf(c0, ah[mt], bh + 0);
                    mma_bf(c1, ah[mt], bh + 2);
                    mma_bf(c0, al[mt], bh + 0);
                    mma_bf(c1, al[mt], bh + 2);
                    mma_bf(c0, ah[mt], bl + 0);
                    mma_bf(c1, ah[mt], bl + 2);
                }
            }
        }
        __syncthreads();
    }

#pragma unroll
    for (int mt = 0; mt < 2; mt++) {
        const size_t r0 = bm + wm * 32 + mt * 16 + (lane >> 2);
#pragma unroll
        for (int nt = 0; nt < 8; nt++) {
            const size_t col = bn + wn * 64 + nt * 8 + (lane & 3) * 2;
            const float* a = &acc[(mt * 8 + nt) * 4];
            float2 v0 = make_float2(a[0], a[1]);
            float2 v1 = make_float2(a[2], a[3]);
            if (BIAS) {
                float2 bv = *(const float2*)&bias[col];
                v0.x += bv.x; v0.y += bv.y;
                v1.x += bv.x; v1.y += bv.y;
            }
            *(float2*)&C[r0 * DD + col] = v0;
            *(float2*)&C[(r0 + 8) * DD + col] = v1;
        }
    }
}

// standalone GEMM kernel for G1
template <bool BIAS>
__global__ void __launch_bounds__(256, 2)
gemm_bf3(const __nv_bfloat16* __restrict__ Ah,
         const __nv_bfloat16* __restrict__ Al,
         const __nv_bfloat16* __restrict__ Bh,
         const __nv_bfloat16* __restrict__ Bl,
         const float* __restrict__ bias, float* __restrict__ C) {
    extern __shared__ __align__(128) char smem[];
    gemm_tile<BIAS>(Ah, Al, Bh, Bl, bias, C,
                    (size_t)blockIdx.y * 128, (size_t)blockIdx.x * 128, smem);
}

// ---------------------------------------------------------------------------
// Fused rnn + G2 kernel.
//   blocks 0..63: recurrence v4 (producer), publishing per-(batch,chunk)
//                 progress every 128 steps.
//   blocks 64..1087: G2 tiles, chunk-major order; each spins on its
//                 (batch,chunk) flag reaching 16 (all heads), then runs the
//                 proven GEMM tile on rows [b*SS + c*128, +128).
// Deadlock-free: rnn blocks (bid<64) are wave-1 resident (64 < 148 SMs even
// at occupancy 1) and depend only on xp (already computed).
// ---------------------------------------------------------------------------
#define HP 136
__global__ void __launch_bounds__(256, 2)
fused_rnn_g2(const float* __restrict__ xp,
             const float* __restrict__ init_state,
             const float* __restrict__ state_w,
             __nv_bfloat16* __restrict__ hs_h,
             __nv_bfloat16* __restrict__ hs_l,
             float* __restrict__ out_state,
             const __nv_bfloat16* __restrict__ WoTh,
             const __nv_bfloat16* __restrict__ WoTl,
             float* __restrict__ out) {
    extern __shared__ __align__(128) char smem[];

    if (blockIdx.x < 64) {
        // ---------------- rnn producer ----------------
        const int b = blockIdx.x >> 4;
        const int n = blockIdx.x & 15;
        const int tid = threadIdx.x;
        const int j = tid >> 1;
        const int half = tid & 1;

        float (*h_sh)[HP] = (float (*)[HP])smem;

        ull w2[32];
        const float* W = state_w + (size_t)n * HH * HH + half * 64 * HH + j;
#pragma unroll
        for (int m = 0; m < 32; m++)
            w2[m] = pack2(W[(2 * m) * HH], W[(2 * m + 1) * HH]);

        const int jpos = j + ((j >> 6) << 2);
        if (half == 0) h_sh[0][jpos] = init_state[b * DD + n * HH + j];

        const float* xb = xp + ((size_t)b * SS * NH + n) * HH + j;
        __nv_bfloat16* hbh = hs_h + ((size_t)b * SS * NH + n) * HH + j;
        __nv_bfloat16* hbl = hs_l + ((size_t)b * SS * NH + n) * HH + j;

        float xq[8];
#pragma unroll
        for (int p = 0; p < 8; p++) xq[p] = xb[(size_t)p * DD];

        __syncthreads();

        const int hbase = half * 68;
        int cur = 0;
        for (int t0 = 0; t0 < SS; t0 += 8) {
#pragma unroll
            for (int u = 0; u < 8; u++) {
                const int t = t0 + u;
                const float xv = xq[u];
                if (t + 8 < SS) xq[u] = xb[(size_t)(t + 8) * DD];

                const ulonglong2* hv = (const ulonglong2*)&h_sh[cur][hbase];
                ull a0 = 0ull, a1 = 0ull, a2 = 0ull, a3 = 0ull;
#pragma unroll
                for (int q = 0; q < 16; q += 4) {
                    ulonglong2 h0 = hv[q + 0];
                    ulonglong2 h1 = hv[q + 1];
                    ulonglong2 h2 = hv[q + 2];
                    ulonglong2 h3 = hv[q + 3];
                    fma2(a0, h0.x, w2[2 * q + 0]);
                    fma2(a1, h0.y, w2[2 * q + 1]);
                    fma2(a2, h1.x, w2[2 * q + 2]);
                    fma2(a3, h1.y, w2[2 * q + 3]);
                    fma2(a0, h2.x, w2[2 * q + 4]);
                    fma2(a1, h2.y, w2[2 * q + 5]);
                    fma2(a2, h3.x, w2[2 * q + 6]);
                    fma2(a3, h3.y, w2[2 * q + 7]);
                }
                float2 f0 = unpack2(a0), f1 = unpack2(a1);
                float2 f2 = unpack2(a2), f3 = unpack2(a3);
                float s = ((f0.x + f0.y) + (f1.x + f1.y)) +
                          ((f2.x + f2.y) + (f3.x + f3.y));
                s += __shfl_xor_sync(0xFFFFFFFFu, s, 1);

                const float hn = fast_tanh(s + xv);
                if (half == 0) h_sh[cur ^ 1][jpos] = hn;
                const __nv_bfloat16 hh = __float2bfloat16(hn);
                if (half == 0) {
                    hbh[(size_t)t * DD] = hh;
                } else {
                    hbl[(size_t)t * DD] =
                        __float2bfloat16(hn - __bfloat162float(hh));
                }
                const bool publish = ((t + 1) & 127) == 0;
                if (publish) __threadfence();   // order hs stores before flag
                __syncthreads();
                if (publish && tid == 0)
                    atomicAdd(&g_cnt[b * 16 + (t >> 7)], 1u);
                cur ^= 1;
            }
        }

        if (out_state && half == 0)
            out_state[b * DD + n * HH + j] = h_sh[cur][jpos];
    } else {
        // ---------------- G2 consumer ----------------
        const int idx = blockIdx.x - 64;
        const int c = idx >> 6;           // s-chunk 0..15 (chunk-major order)
        const int b = (idx >> 4) & 3;
        const int nt = idx & 15;

        if (threadIdx.x == 0) {
            unsigned* flag = &g_cnt[b * 16 + c];
            while (atomicAdd(flag, 0u) < 16u) __nanosleep(256);
            __threadfence();              // acquire hs stores
        }
        __syncthreads();

        gemm_tile<false>(hs_h, hs_l, WoTh, WoTl, nullptr, out,
                         (size_t)b * SS + (size_t)c * 128,
                         (size_t)nt * 128, smem);
    }
}

// ---------------------------------------------------------------------------
extern "C" void kernel_launch(void* const* d_in, const int* in_sizes, int n_in,
                              void* d_out, int out_size) {
    const float* x = (const float*)d_in[0];
    const float* input_state = (const float*)d_in[1];
    const float* Wi = (const float*)d_in[2];
    const float* bias = (const float*)d_in[3];
    const float* state_w = (const float*)d_in[4];
    const float* Wo = (const float*)d_in[5];
    float* out = (float*)d_out;

    float* xp = nullptr;
    __nv_bfloat16 *xh, *xl, *hsh, *hsl, *WiTh, *WiTl, *WoTh, *WoTl;
    cudaGetSymbolAddress((void**)&xp, g_xp);
    cudaGetSymbolAddress((void**)&xh, g_xh);
    cudaGetSymbolAddress((void**)&xl, g_xl);
    cudaGetSymbolAddress((void**)&hsh, g_hsh);
    cudaGetSymbolAddress((void**)&hsl, g_hsl);
    cudaGetSymbolAddress((void**)&WiTh, g_WiTh);
    cudaGetSymbolAddress((void**)&WiTl, g_WiTl);
    cudaGetSymbolAddress((void**)&WoTh, g_WoTh);
    cudaGetSymbolAddress((void**)&WoTl, g_WoTl);

    cudaFuncSetAttribute(gemm_bf3<true>,
                         cudaFuncAttributeMaxDynamicSharedMemorySize, SMEMB);
    cudaFuncSetAttribute(fused_rnn_g2,
                         cudaFuncAttributeMaxDynamicSharedMemorySize, SMEMB);

    const size_t out_elems = (size_t)BB * SS * DD;
    float* state_out = nullptr;
    if ((size_t)out_size >= out_elems + (size_t)BB * DD)
        state_out = out + out_elems;

    // 0) operand preparation + progress-flag reset
    split_f32<<<(BB * SS * DD) / 4 / 256, 256>>>(
        (const float4*)x, (__nv_bfloat162*)xh, (__nv_bfloat162*)xl);
    dim3 tgrid(DD / 32, DD / 32), tblk(32, 8);
    transpose_split<<<tgrid, tblk>>>(Wi, WiTh, WiTl);
    transpose_split<<<tgrid, tblk>>>(Wo, WoTh, WoTl);
    cnt_reset<<<1, BB * 16>>>();

    // 1) xp = x @ Wi + b
    dim3 ggrid(DD / 128, (BB * SS) / 128);  // (16, 64)
    gemm_bf3<true><<<ggrid, 256, SMEMB>>>(xh, xl, WiTh, WiTl, bias, xp);

    // 2+3) fused: recurrence (blocks 0-63) overlapped with out = hs @ Wo
    //      (blocks 64-1087, gated per (batch, s-chunk))
    fused_rnn_g2<<<64 + 1024, 256, SMEMB>>>(
        xp, input_state, state_w, hsh, hsl, state_out, WoTh, WoTl, out);
}